// round 9
// baseline (speedup 1.0000x reference)
#include <cuda_runtime.h>
#include <math.h>
#include <stdint.h>

static constexpr int B = 8, C = 256, E = 64, N = 4096;

__device__ float g_fT[B * N * E];  // key  [b][n][slot(e)]  tf32-rounded + interleaved
__device__ float g_gT[B * N * E];  // query [b][n][e] raw
__device__ float g_hE[B * E * N];  // value [b][e][n-interleaved per 64-block]
__device__ float g_vT[B * N * E];  // attn out [b][n][e]

// ---------------- helpers ----------------
__device__ __forceinline__ uint32_t smem_u32(const void* p) {
    uint32_t a;
    asm("{ .reg .u64 t; cvta.to.shared.u64 t, %1; cvt.u32.u64 %0, t; }" : "=r"(a) : "l"(p));
    return a;
}
__device__ __forceinline__ void cpasync16(uint32_t dst, const void* src) {
    asm volatile("cp.async.cg.shared.global [%0], [%1], 16;" :: "r"(dst), "l"(src));
}
#define CP_COMMIT() asm volatile("cp.async.commit_group;" ::: "memory")
#define CP_WAIT0()  asm volatile("cp.async.wait_group 0;" ::: "memory")

__device__ __forceinline__ uint32_t to_tf32(float v) {
    uint32_t u;
    asm("cvt.rna.tf32.f32 %0, %1;" : "=r"(u) : "f"(v));
    return u;
}
__device__ __forceinline__ float tf32f(float v) {
    return __uint_as_float(to_tf32(v));
}
// interleave slot: (k, k+4) fragment pairs land adjacent
__device__ __forceinline__ int islot(int e) {
    return ((e >> 3) << 3) | (2 * (e & 3)) | ((e >> 2) & 1);
}
// D += A(16x8) * B(8x8), tf32 inputs, fp32 accum
__device__ __forceinline__ void mma8(float* d, const uint32_t* a, const uint32_t* b) {
    asm volatile(
        "mma.sync.aligned.m16n8k8.row.col.f32.tf32.tf32.f32 "
        "{%0,%1,%2,%3}, {%4,%5,%6,%7}, {%8,%9}, {%0,%1,%2,%3};"
        : "+f"(d[0]), "+f"(d[1]), "+f"(d[2]), "+f"(d[3])
        : "r"(a[0]), "r"(a[1]), "r"(a[2]), "r"(a[3]), "r"(b[0]), "r"(b[1]));
}

// ---------------------------------------------------------------------------
// Projection GEMM [192,256] x [256, 64-col tile]; 8x4 microtile per thread.
// Emits K pre-rounded+interleaved and V n-interleaved for the flash kernel.
// grid (N/64, B), 384 threads, 67584 B dyn smem, 2 CTAs/SM.
// ---------------------------------------------------------------------------
__global__ __launch_bounds__(384, 2) void proj_kernel(
    const float* __restrict__ x,
    const float* __restrict__ wk, const float* __restrict__ bk,
    const float* __restrict__ wq, const float* __restrict__ bq,
    const float* __restrict__ wv, const float* __restrict__ bv)
{
    extern __shared__ float psm[];
    float* xs = psm;              // [64 c][68 n]
    float* ws = psm + 64 * 68;    // [64 c][196 r]

    const int b  = blockIdx.y;
    const int n0 = blockIdx.x << 6;
    const int tid = threadIdx.x;
    const float* xb = x + (size_t)b * C * N;
    const int rg = tid >> 4;      // 8-row group (0..23)
    const int cg = tid & 15;      // 4-col group

    float acc[8][4];
    #pragma unroll
    for (int i = 0; i < 8; i++)
        #pragma unroll
        for (int j = 0; j < 4; j++) acc[i][j] = 0.f;

    for (int c0 = 0; c0 < C; c0 += 64) {
        __syncthreads();
        for (int i = tid; i < 1024; i += 384) {
            int c = i >> 4, n4 = (i & 15) << 2;
            *(float4*)&xs[c * 68 + n4] = *(const float4*)&xb[(size_t)(c0 + c) * N + n0 + n4];
        }
        for (int i = tid; i < 12288; i += 384) {
            int r = i >> 6, c = i & 63;
            float v;
            if (r < 64)       v = wk[r * C + c0 + c];
            else if (r < 128) v = wq[(r - 64) * C + c0 + c];
            else              v = wv[(r - 128) * C + c0 + c];
            ws[c * 196 + r] = v;
        }
        __syncthreads();
        #pragma unroll 4
        for (int c = 0; c < 64; ++c) {
            float4 xv = *(float4*)&xs[c * 68 + (cg << 2)];
            const float4* wp = (const float4*)&ws[c * 196 + rg * 8];
            float4 w0 = wp[0], w1 = wp[1];
            float wr[8] = {w0.x, w0.y, w0.z, w0.w, w1.x, w1.y, w1.z, w1.w};
            #pragma unroll
            for (int i = 0; i < 8; i++) {
                acc[i][0] += wr[i] * xv.x; acc[i][1] += wr[i] * xv.y;
                acc[i][2] += wr[i] * xv.z; acc[i][3] += wr[i] * xv.w;
            }
        }
    }
    #pragma unroll
    for (int i = 0; i < 8; i++) {
        int r = rg * 8 + i;
        float bias = (r < 64) ? bk[r] : (r < 128 ? bq[r - 64] : bv[r - 128]);
        #pragma unroll
        for (int j = 0; j < 4; j++) {
            int n = n0 + (cg << 2) + j;
            float v = acc[i][j] * 0.0625f + bias;
            if (r < 64) {
                // K: tf32-rounded, e-interleaved
                g_fT[((size_t)b * N + n) * E + islot(r)] = tf32f(v);
            } else if (r < 128) {
                g_gT[((size_t)b * N + n) * E + (r - 64)] = v;
            } else {
                // V: n-interleaved within its 64-block
                int np = (n & ~63) | islot(n & 63);
                g_hE[((size_t)b * E + (r - 128)) * N + np] = v;
            }
        }
    }
}

// ---------------------------------------------------------------------------
// Flash attention, mma.sync tf32. K & V arrive pre-interleaved from proj;
// all staging is cp.async, double-buffered, one barrier per tile.
// Fragment loads: K pitch 72 LDS.64, V pitch 68 LDS.64 (both conflict-free).
// CTA: 256 thr = 8 warps x 16 q-rows (BLOCK_M=128), BLOCK_N=64, 64 tiles.
// smem floats: K 2x[64][72], V 2x[64][68], Ps [128][72] = 108544 B, 2 CTAs/SM.
// ---------------------------------------------------------------------------
static constexpr int KS0 = 0;        // K buffer b at KS0 + b*4608
static constexpr int VS0 = 9216;     // V buffer b at VS0 + b*4352
static constexpr int PS0 = 17920;    // Ps [128][72]
static constexpr int NT  = N / 64;   // 64 key tiles

__global__ __launch_bounds__(256, 2) void flash_mma()
{
    extern __shared__ float fsm[];
    const int tid = threadIdx.x;
    const int lane = tid & 31, w = tid >> 5;
    const int tig = lane & 3, gid = lane >> 2;   // mma frag coords
    const int b = blockIdx.y, q0 = blockIdx.x << 7;

    const float* Kg = g_fT + (size_t)b * N * E;
    const float* Vg = g_hE + (size_t)b * E * N;
    const float* Qg = g_gT + ((size_t)b * N + q0) * E;

    const int rowf = tid >> 2, cbf = (tid & 3) << 2;  // staging coords

    // stage Q (raw fp32) into Ps (pitch 72), K/V tile 0 into buffer 0
    for (int i = tid; i < 2048; i += 256) {
        int row = i >> 4, c4 = (i & 15) << 2;
        cpasync16(smem_u32(fsm + PS0 + row * 72 + c4), Qg + row * 64 + c4);
    }
    #pragma unroll
    for (int i = 0; i < 4; i++) {
        cpasync16(smem_u32(fsm + KS0 + rowf * 72 + cbf + 16 * i),
                  Kg + (size_t)rowf * 64 + cbf + 16 * i);
        cpasync16(smem_u32(fsm + VS0 + rowf * 68 + cbf + 16 * i),
                  Vg + (size_t)rowf * N + cbf + 16 * i);
    }
    CP_COMMIT();
    CP_WAIT0();
    __syncthreads();

    // Q fragments (tf32), register resident: 32 regs
    uint32_t qt[8][4];
    {
        const float* Qs = fsm + PS0 + (w * 16) * 72;
        #pragma unroll
        for (int ks = 0; ks < 8; ks++) {
            int e = tig + 8 * ks;
            qt[ks][0] = to_tf32(Qs[gid * 72 + e]);
            qt[ks][1] = to_tf32(Qs[(gid + 8) * 72 + e]);
            qt[ks][2] = to_tf32(Qs[gid * 72 + e + 4]);
            qt[ks][3] = to_tf32(Qs[(gid + 8) * 72 + e + 4]);
        }
    }
    __syncthreads();   // Ps free for P staging

    float O[8][4];
    #pragma unroll
    for (int j = 0; j < 8; j++)
        #pragma unroll
        for (int i = 0; i < 4; i++) O[j][i] = 0.f;
    float m0 = -1e30f, m1 = -1e30f, l0 = 0.f, l1 = 0.f;

    const int r0 = w * 16 + gid;
    float* rp  = fsm + PS0 + r0 * 72;   // own q-row in Ps
    float* rp8 = rp + 8 * 72;
    const int bse = ((tig & 1) << 2) | (tig >> 1);   // P write slot base

    for (int t = 0; t < NT; ++t) {
        const int buf = t & 1, nb = buf ^ 1;
        const bool pref = (t < NT - 1);
        const int k0n = (t + 1) << 6;

        // async K+V prefetch for next tile (other buffers)
        if (pref) {
            #pragma unroll
            for (int i = 0; i < 4; i++) {
                cpasync16(smem_u32(fsm + KS0 + nb * 4608 + rowf * 72 + cbf + 16 * i),
                          Kg + (size_t)(k0n + rowf) * 64 + cbf + 16 * i);
                cpasync16(smem_u32(fsm + VS0 + nb * 4352 + rowf * 68 + cbf + 16 * i),
                          Vg + (size_t)rowf * N + k0n + cbf + 16 * i);
            }
            CP_COMMIT();
        }

        // ---- S = qt * K  (interleaved, single LDS.64 per mma) ----
        float S[8][4];
        #pragma unroll
        for (int j = 0; j < 8; j++)
            #pragma unroll
            for (int i = 0; i < 4; i++) S[j][i] = 0.f;
        {
            const float* Kh = fsm + KS0 + buf * 4608;
            #pragma unroll
            for (int ks = 0; ks < 8; ks++) {
                int off = 8 * ks + 2 * tig;
                #pragma unroll
                for (int j = 0; j < 8; j++) {
                    float2 kk = *(const float2*)&Kh[(gid + 8 * j) * 72 + off];
                    uint32_t bb[2] = {__float_as_uint(kk.x), __float_as_uint(kk.y)};
                    mma8(S[j], qt[ks], bb);
                }
            }
        }

        // ---- online softmax (rows r0 and r0+8) ----
        float c0m = -1e30f, c1m = -1e30f;
        #pragma unroll
        for (int j = 0; j < 8; j++) {
            c0m = fmaxf(c0m, fmaxf(S[j][0], S[j][1]));
            c1m = fmaxf(c1m, fmaxf(S[j][2], S[j][3]));
        }
        c0m = fmaxf(c0m, __shfl_xor_sync(0xffffffffu, c0m, 1));
        c0m = fmaxf(c0m, __shfl_xor_sync(0xffffffffu, c0m, 2));
        c1m = fmaxf(c1m, __shfl_xor_sync(0xffffffffu, c1m, 1));
        c1m = fmaxf(c1m, __shfl_xor_sync(0xffffffffu, c1m, 2));
        float mn0 = fmaxf(m0, c0m), mn1 = fmaxf(m1, c1m);
        bool need = (mn0 > m0) || (mn1 > m1);
        float a0 = __expf(m0 - mn0), a1 = __expf(m1 - mn1);
        m0 = mn0; m1 = mn1;

        float s0 = 0.f, s1 = 0.f;
        #pragma unroll
        for (int j = 0; j < 8; j++) {
            float p00 = __expf(S[j][0] - m0), p01 = __expf(S[j][1] - m0);
            float p10 = __expf(S[j][2] - m1), p11 = __expf(S[j][3] - m1);
            s0 += p00 + p01; s1 += p10 + p11;
            rp [8 * j + bse]     = tf32f(p00);
            rp [8 * j + bse + 2] = tf32f(p01);
            rp8[8 * j + bse]     = tf32f(p10);
            rp8[8 * j + bse + 2] = tf32f(p11);
        }
        s0 += __shfl_xor_sync(0xffffffffu, s0, 1);
        s0 += __shfl_xor_sync(0xffffffffu, s0, 2);
        s1 += __shfl_xor_sync(0xffffffffu, s1, 1);
        s1 += __shfl_xor_sync(0xffffffffu, s1, 2);
        l0 = l0 * a0 + s0;
        l1 = l1 * a1 + s1;
        if (__any_sync(0xffffffffu, need)) {   // lazy rescale
            #pragma unroll
            for (int j = 0; j < 8; j++) {
                O[j][0] *= a0; O[j][1] *= a0; O[j][2] *= a1; O[j][3] *= a1;
            }
        }
        __syncwarp();   // P visible within warp

        // ---- O += P V^T  (V interleaved pitch 68, single LDS.64 per mma) ----
        {
            const float* Vs = fsm + VS0 + buf * 4352;
            #pragma unroll
            for (int ks = 0; ks < 8; ks++) {
                int off = 8 * ks + 2 * tig;
                float2 pA = *(const float2*)&rp[off];    // {pa0, pa2}
                float2 pB = *(const float2*)&rp8[off];   // {pa1, pa3}
                uint32_t pa[4] = {__float_as_uint(pA.x), __float_as_uint(pB.x),
                                  __float_as_uint(pA.y), __float_as_uint(pB.y)};
                #pragma unroll
                for (int j = 0; j < 8; j++) {
                    float2 vv = *(const float2*)&Vs[(gid + 8 * j) * 68 + off];
                    uint32_t vb[2] = {__float_as_uint(vv.x), __float_as_uint(vv.y)};
                    mma8(O[j], pa, vb);
                }
            }
        }

        CP_WAIT0();
        __syncthreads();   // single barrier per tile
    }

    // ---- epilogue: O/l -> Ps -> gmem ----
    {
        float i0 = 1.f / l0, i1 = 1.f / l1;
        #pragma unroll
        for (int j = 0; j < 8; j++) {
            int col = 8 * j + 2 * tig;
            *(float2*)&rp[col]  = make_float2(O[j][0] * i0, O[j][1] * i0);
            *(float2*)&rp8[col] = make_float2(O[j][2] * i1, O[j][3] * i1);
        }
    }
    __syncthreads();
    {
        float* dst = g_vT + ((size_t)b * N + q0) * E;
        for (int i = tid; i < 2048; i += 256) {
            int row = i >> 4, c4 = (i & 15) << 2;
            *(float4*)(dst + (size_t)row * 64 + c4) = *(float4*)(fsm + PS0 + row * 72 + c4);
        }
    }
}

// ---------------------------------------------------------------------------
// Output: y = gamma * (w_att @ v / 8 + b_att) + x   (unchanged, known-good)
// ---------------------------------------------------------------------------
__global__ __launch_bounds__(256) void out_kernel(
    const float* __restrict__ x, const float* __restrict__ w_att,
    const float* __restrict__ b_att, const float* __restrict__ gamma,
    float* __restrict__ y)
{
    extern __shared__ float sm[];
    float* ws = sm;               // [256][64]
    float* as = sm + 256 * 64;    // [64][68]
    int b = blockIdx.y, n0 = blockIdx.x << 6;
    int tid = threadIdx.x;

    float4* ws4 = (float4*)ws;
    const float4* wg4 = (const float4*)w_att;
    for (int idx = tid; idx < 4096; idx += 256) ws4[idx] = wg4[idx];
    const float* src = g_vT + ((size_t)b * N + n0) * E;
    for (int idx = tid; idx < 4096; idx += 256) {
        int nl = idx >> 6, e = idx & 63;
        as[nl * 68 + e] = src[idx];
    }
    __syncthreads();

    int tx = tid & 63, ty = tid >> 6;
    const float* xcol = x + ((size_t)b * C) * N + n0 + tx;
    float* ycol = y + ((size_t)b * C) * N + n0 + tx;
    const float4* a4 = (const float4*)&as[tx * 68];

    for (int m0 = 0; m0 < 64; m0 += 4) {
        float acc[4] = {0.f, 0.f, 0.f, 0.f};
        #pragma unroll
        for (int e4 = 0; e4 < 16; e4++) {
            float4 a = a4[e4];
            #pragma unroll
            for (int mi = 0; mi < 4; mi++) {
                int c = ty + 4 * (m0 + mi);
                float4 wv = ((const float4*)(ws + c * 64))[e4];
                acc[mi] += a.x * wv.x + a.y * wv.y + a.z * wv.z + a.w * wv.w;
            }
        }
        #pragma unroll
        for (int mi = 0; mi < 4; mi++) {
            int c = ty + 4 * (m0 + mi);
            float o = acc[mi] * 0.125f + b_att[c];
            ycol[(size_t)c * N] = gamma[c] * o + xcol[(size_t)c * N];
        }
    }
}

// ---------------------------------------------------------------------------
extern "C" void kernel_launch(void* const* d_in, const int* in_sizes, int n_in,
                              void* d_out, int out_size)
{
    const float* x  = (const float*)d_in[0];
    const float* wk = (const float*)d_in[1];
    const float* bk = (const float*)d_in[2];
    const float* wq = (const float*)d_in[3];
    const float* bq = (const float*)d_in[4];
    const float* wv = (const float*)d_in[5];
    const float* bv = (const float*)d_in[6];
    const float* wa = (const float*)d_in[7];
    const float* ba = (const float*)d_in[8];
    const float* gm = (const float*)d_in[9];
    float* y = (float*)d_out;

    cudaFuncSetAttribute(proj_kernel, cudaFuncAttributeMaxDynamicSharedMemorySize, 69632);
    cudaFuncSetAttribute(flash_mma,  cudaFuncAttributeMaxDynamicSharedMemorySize, 108544);
    cudaFuncSetAttribute(out_kernel, cudaFuncAttributeMaxDynamicSharedMemorySize, 84000);

    proj_kernel<<<dim3(N / 64, B), 384, 67584>>>(x, wk, bk, wq, bq, wv, bv);
    flash_mma<<<dim3(N / 128, B), 256, 108544>>>();
    out_kernel<<<dim3(N / 64, B), 256, 82944>>>(x, wa, ba, gm, y);
}

// round 10
// speedup vs baseline: 1.6769x; 1.6769x over previous
#include <cuda_runtime.h>
#include <cuda_fp16.h>
#include <math.h>
#include <stdint.h>

static constexpr int B = 8, C = 256, E = 64, N = 4096;

__device__ __half g_fK[B * N * E];  // key   [b][n][islot_h(e)] fp16
__device__ float  g_gT[B * N * E];  // query [b][n][e] fp32
__device__ __half g_hV[B * E * N];  // value [b][e][islot_h within n-16-block] fp16
__device__ float  g_vT[B * N * E];  // attn out [b][n][e]

// ---------------- helpers ----------------
__device__ __forceinline__ uint32_t smem_u32(const void* p) {
    uint32_t a;
    asm("{ .reg .u64 t; cvta.to.shared.u64 t, %1; cvt.u32.u64 %0, t; }" : "=r"(a) : "l"(p));
    return a;
}
__device__ __forceinline__ void cpasync16(uint32_t dst, const void* src) {
    asm volatile("cp.async.cg.shared.global [%0], [%1], 16;" :: "r"(dst), "l"(src));
}
#define CP_COMMIT() asm volatile("cp.async.commit_group;" ::: "memory")
#define CP_WAIT0()  asm volatile("cp.async.wait_group 0;" ::: "memory")

// pack two f32 -> f16x2 (lo first)
__device__ __forceinline__ uint32_t h2pack(float lo, float hi) {
    uint32_t r;
    asm("cvt.rn.f16x2.f32 %0, %1, %2;" : "=r"(r) : "f"(hi), "f"(lo));
    return r;
}
// interleave within 16-block: pair order [0,4,1,5,2,6,3,7]
__device__ __forceinline__ int islot_h(int e) {
    int c = e & 15, pair = c >> 1;
    int pos = 2 * (pair & 3) + (pair >> 2);
    return (e & ~15) | (pos << 1) | (c & 1);
}
// D += A(16x16) * B(16x8), fp16 inputs, fp32 accum
__device__ __forceinline__ void mma16(float* d, const uint32_t* a, uint32_t b0, uint32_t b1) {
    asm volatile(
        "mma.sync.aligned.m16n8k16.row.col.f32.f16.f16.f32 "
        "{%0,%1,%2,%3}, {%4,%5,%6,%7}, {%8,%9}, {%0,%1,%2,%3};"
        : "+f"(d[0]), "+f"(d[1]), "+f"(d[2]), "+f"(d[3])
        : "r"(a[0]), "r"(a[1]), "r"(a[2]), "r"(a[3]), "r"(b0), "r"(b1));
}

// ---------------------------------------------------------------------------
// Projection GEMM [192,256] x [256, 64-col tile]; 8x4 microtile per thread.
// Emits K/V fp16 pre-interleaved for the flash kernel, Q raw fp32.
// grid (N/64, B), 384 threads, 67584 B dyn smem, 2 CTAs/SM.
// ---------------------------------------------------------------------------
__global__ __launch_bounds__(384, 2) void proj_kernel(
    const float* __restrict__ x,
    const float* __restrict__ wk, const float* __restrict__ bk,
    const float* __restrict__ wq, const float* __restrict__ bq,
    const float* __restrict__ wv, const float* __restrict__ bv)
{
    extern __shared__ float psm[];
    float* xs = psm;              // [64 c][68 n]
    float* ws = psm + 64 * 68;    // [64 c][196 r]

    const int b  = blockIdx.y;
    const int n0 = blockIdx.x << 6;
    const int tid = threadIdx.x;
    const float* xb = x + (size_t)b * C * N;
    const int rg = tid >> 4;      // 8-row group (0..23)
    const int cg = tid & 15;      // 4-col group

    float acc[8][4];
    #pragma unroll
    for (int i = 0; i < 8; i++)
        #pragma unroll
        for (int j = 0; j < 4; j++) acc[i][j] = 0.f;

    for (int c0 = 0; c0 < C; c0 += 64) {
        __syncthreads();
        for (int i = tid; i < 1024; i += 384) {
            int c = i >> 4, n4 = (i & 15) << 2;
            *(float4*)&xs[c * 68 + n4] = *(const float4*)&xb[(size_t)(c0 + c) * N + n0 + n4];
        }
        for (int i = tid; i < 12288; i += 384) {
            int r = i >> 6, c = i & 63;
            float v;
            if (r < 64)       v = wk[r * C + c0 + c];
            else if (r < 128) v = wq[(r - 64) * C + c0 + c];
            else              v = wv[(r - 128) * C + c0 + c];
            ws[c * 196 + r] = v;
        }
        __syncthreads();
        #pragma unroll 4
        for (int c = 0; c < 64; ++c) {
            float4 xv = *(float4*)&xs[c * 68 + (cg << 2)];
            const float4* wp = (const float4*)&ws[c * 196 + rg * 8];
            float4 w0 = wp[0], w1 = wp[1];
            float wr[8] = {w0.x, w0.y, w0.z, w0.w, w1.x, w1.y, w1.z, w1.w};
            #pragma unroll
            for (int i = 0; i < 8; i++) {
                acc[i][0] += wr[i] * xv.x; acc[i][1] += wr[i] * xv.y;
                acc[i][2] += wr[i] * xv.z; acc[i][3] += wr[i] * xv.w;
            }
        }
    }

    const int rbase = rg * 8;
    if (rg < 8) {
        // K: rows rbase..rbase+7 (e-index), fp16, e-interleaved pairs
        #pragma unroll
        for (int j = 0; j < 4; j++) {
            int n = n0 + (cg << 2) + j;
            size_t base = ((size_t)b * N + n) * (size_t)E;
            #pragma unroll
            for (int i = 0; i < 8; i += 2) {
                int r = rbase + i;
                float v0 = acc[i][j]     * 0.0625f + bk[r];
                float v1 = acc[i + 1][j] * 0.0625f + bk[r + 1];
                *(uint32_t*)(g_fK + base + islot_h(r)) = h2pack(v0, v1);
            }
        }
    } else if (rg < 16) {
        #pragma unroll
        for (int i = 0; i < 8; i++) {
            int e = rbase + i - 64;
            float bias = bq[e];
            #pragma unroll
            for (int j = 0; j < 4; j++) {
                int n = n0 + (cg << 2) + j;
                g_gT[((size_t)b * N + n) * E + e] = acc[i][j] * 0.0625f + bias;
            }
        }
    } else {
        // V: fp16, n-interleaved pairs
        #pragma unroll
        for (int i = 0; i < 8; i++) {
            int e = rbase + i - 128;
            float bias = bv[e];
            size_t rowb = ((size_t)b * E + e) * (size_t)N;
            #pragma unroll
            for (int j = 0; j < 4; j += 2) {
                int n = n0 + (cg << 2) + j;
                float v0 = acc[i][j]     * 0.0625f + bias;
                float v1 = acc[i][j + 1] * 0.0625f + bias;
                *(uint32_t*)(g_hV + rowb + islot_h(n)) = h2pack(v0, v1);
            }
        }
    }
}

// ---------------------------------------------------------------------------
// Flash attention, mma.sync fp16 m16n8k16 (fp32 accum). P stays in registers
// (D-frag of S == A-frag of PV). K/V pre-interleaved fp16, double-buffered.
// CTA: 256 thr = 8 warps x 16 q-rows (BLOCK_M=128), BLOCK_N=64, 64 tiles.
// smem: K 2x[64][80]h + V 2x[64][80]h + Ps[128][72]f = 77824 B, 2 CTAs/SM.
// ---------------------------------------------------------------------------
static constexpr int KHALF = 5120;    // halves per K/V buffer (64*80)
static constexpr int NT = N / 64;     // 64 key tiles

__global__ __launch_bounds__(256, 2) void flash_mma()
{
    extern __shared__ char sraw[];
    __half* Ks = (__half*)sraw;                 // 2 bufs, pitch 80 halves
    __half* Vs = (__half*)(sraw + 20480);       // 2 bufs, pitch 80 halves
    float*  Ps = (float*)(sraw + 40960);        // [128][72]

    const int tid = threadIdx.x;
    const int lane = tid & 31, w = tid >> 5;
    const int tig = lane & 3, gid = lane >> 2;   // mma frag coords
    const int b = blockIdx.y, q0 = blockIdx.x << 7;

    const __half* Kg = g_fK + (size_t)b * N * E;
    const __half* Vg = g_hV + (size_t)b * E * N;
    const float*  Qg = g_gT + ((size_t)b * N + q0) * E;

    const int srow = tid >> 3, schunk = (tid & 7) << 3;  // 8 thr/row, 16B chunks

    // stage Q (fp32) into Ps, K/V tile 0 into buffer 0
    for (int i = tid; i < 2048; i += 256) {
        int row = i >> 4, c4 = (i & 15) << 2;
        cpasync16(smem_u32(Ps + row * 72 + c4), Qg + row * 64 + c4);
    }
    #pragma unroll
    for (int p = 0; p < 2; p++) {
        int row = srow + 32 * p;
        cpasync16(smem_u32(Ks + row * 80 + schunk), Kg + (size_t)row * 64 + schunk);
        cpasync16(smem_u32(Vs + row * 80 + schunk), Vg + (size_t)row * N + schunk);
    }
    CP_COMMIT();
    CP_WAIT0();
    __syncthreads();

    // Q fragments (fp16x2), register resident: 16 regs
    uint32_t qa[4][4];
    {
        const float* Qs = Ps + (w * 16) * 72;
        #pragma unroll
        for (int ks = 0; ks < 4; ks++) {
            int e0 = 16 * ks + 2 * tig;
            qa[ks][0] = h2pack(Qs[gid * 72 + e0],           Qs[gid * 72 + e0 + 1]);
            qa[ks][1] = h2pack(Qs[(gid + 8) * 72 + e0],     Qs[(gid + 8) * 72 + e0 + 1]);
            qa[ks][2] = h2pack(Qs[gid * 72 + e0 + 8],       Qs[gid * 72 + e0 + 9]);
            qa[ks][3] = h2pack(Qs[(gid + 8) * 72 + e0 + 8], Qs[(gid + 8) * 72 + e0 + 9]);
        }
    }
    __syncthreads();

    float O[8][4];
    #pragma unroll
    for (int j = 0; j < 8; j++)
        #pragma unroll
        for (int i = 0; i < 4; i++) O[j][i] = 0.f;
    float m0 = -1e30f, m1 = -1e30f, l0 = 0.f, l1 = 0.f;

    for (int t = 0; t < NT; ++t) {
        const int buf = t & 1, nb = buf ^ 1;
        const bool pref = (t < NT - 1);
        const int k0n = (t + 1) << 6;

        // async K+V prefetch for next tile
        if (pref) {
            #pragma unroll
            for (int p = 0; p < 2; p++) {
                int row = srow + 32 * p;
                cpasync16(smem_u32(Ks + nb * KHALF + row * 80 + schunk),
                          Kg + (size_t)(k0n + row) * 64 + schunk);
                cpasync16(smem_u32(Vs + nb * KHALF + row * 80 + schunk),
                          Vg + (size_t)row * N + k0n + schunk);
            }
            CP_COMMIT();
        }

        // ---- S = Q K^T  (fp16 k16, one LDS.64 per mma) ----
        float S[8][4];
        #pragma unroll
        for (int j = 0; j < 8; j++)
            #pragma unroll
            for (int i = 0; i < 4; i++) S[j][i] = 0.f;
        {
            const __half* Kh = Ks + buf * KHALF;
            #pragma unroll
            for (int ks = 0; ks < 4; ks++) {
                int off = ks * 16 + tig * 4;
                #pragma unroll
                for (int j = 0; j < 8; j++) {
                    uint2 bb = *(const uint2*)&Kh[(gid + 8 * j) * 80 + off];
                    mma16(S[j], qa[ks], bb.x, bb.y);
                }
            }
        }

        // ---- online softmax (rows r0 = w*16+gid and +8) ----
        float c0m = -1e30f, c1m = -1e30f;
        #pragma unroll
        for (int j = 0; j < 8; j++) {
            c0m = fmaxf(c0m, fmaxf(S[j][0], S[j][1]));
            c1m = fmaxf(c1m, fmaxf(S[j][2], S[j][3]));
        }
        c0m = fmaxf(c0m, __shfl_xor_sync(0xffffffffu, c0m, 1));
        c0m = fmaxf(c0m, __shfl_xor_sync(0xffffffffu, c0m, 2));
        c1m = fmaxf(c1m, __shfl_xor_sync(0xffffffffu, c1m, 1));
        c1m = fmaxf(c1m, __shfl_xor_sync(0xffffffffu, c1m, 2));
        float mn0 = fmaxf(m0, c0m), mn1 = fmaxf(m1, c1m);
        bool need = (mn0 > m0) || (mn1 > m1);
        float a0 = __expf(m0 - mn0), a1 = __expf(m1 - mn1);
        m0 = mn0; m1 = mn1;

        float s0 = 0.f, s1 = 0.f;
        #pragma unroll
        for (int j = 0; j < 8; j++) {
            S[j][0] = __expf(S[j][0] - m0); S[j][1] = __expf(S[j][1] - m0);
            S[j][2] = __expf(S[j][2] - m1); S[j][3] = __expf(S[j][3] - m1);
            s0 += S[j][0] + S[j][1];
            s1 += S[j][2] + S[j][3];
        }
        s0 += __shfl_xor_sync(0xffffffffu, s0, 1);
        s0 += __shfl_xor_sync(0xffffffffu, s0, 2);
        s1 += __shfl_xor_sync(0xffffffffu, s1, 1);
        s1 += __shfl_xor_sync(0xffffffffu, s1, 2);
        l0 = l0 * a0 + s0;
        l1 = l1 * a1 + s1;
        if (__any_sync(0xffffffffu, need)) {   // lazy rescale
            #pragma unroll
            for (int j = 0; j < 8; j++) {
                O[j][0] *= a0; O[j][1] *= a0; O[j][2] *= a1; O[j][3] *= a1;
            }
        }

        // ---- O += P V^T  (P = registers: S D-frag == PV A-frag) ----
        {
            const __half* Vh = Vs + buf * KHALF;
            #pragma unroll
            for (int m = 0; m < 4; m++) {
                uint32_t pa[4] = {
                    h2pack(S[2 * m][0],     S[2 * m][1]),
                    h2pack(S[2 * m][2],     S[2 * m][3]),
                    h2pack(S[2 * m + 1][0], S[2 * m + 1][1]),
                    h2pack(S[2 * m + 1][2], S[2 * m + 1][3])
                };
                int off = m * 16 + tig * 4;
                #pragma unroll
                for (int j = 0; j < 8; j++) {
                    uint2 vv = *(const uint2*)&Vh[(gid + 8 * j) * 80 + off];
                    mma16(O[j], pa, vv.x, vv.y);
                }
            }
        }

        CP_WAIT0();
        __syncthreads();   // single barrier per tile
    }

    // ---- epilogue: O/l -> Ps -> gmem ----
    {
        const int r0 = w * 16 + gid;
        float* rp  = Ps + r0 * 72;
        float* rp8 = rp + 8 * 72;
        float i0 = 1.f / l0, i1 = 1.f / l1;
        #pragma unroll
        for (int j = 0; j < 8; j++) {
            int col = 8 * j + 2 * tig;
            *(float2*)&rp[col]  = make_float2(O[j][0] * i0, O[j][1] * i0);
            *(float2*)&rp8[col] = make_float2(O[j][2] * i1, O[j][3] * i1);
        }
    }
    __syncthreads();
    {
        float* dst = g_vT + ((size_t)b * N + q0) * E;
        for (int i = tid; i < 2048; i += 256) {
            int row = i >> 4, c4 = (i & 15) << 2;
            *(float4*)(dst + (size_t)row * 64 + c4) = *(float4*)(Ps + row * 72 + c4);
        }
    }
}

// ---------------------------------------------------------------------------
// Output: y = gamma * (w_att @ v / 8 + b_att) + x   (unchanged, known-good)
// ---------------------------------------------------------------------------
__global__ __launch_bounds__(256) void out_kernel(
    const float* __restrict__ x, const float* __restrict__ w_att,
    const float* __restrict__ b_att, const float* __restrict__ gamma,
    float* __restrict__ y)
{
    extern __shared__ float sm[];
    float* ws = sm;               // [256][64]
    float* as = sm + 256 * 64;    // [64][68]
    int b = blockIdx.y, n0 = blockIdx.x << 6;
    int tid = threadIdx.x;

    float4* ws4 = (float4*)ws;
    const float4* wg4 = (const float4*)w_att;
    for (int idx = tid; idx < 4096; idx += 256) ws4[idx] = wg4[idx];
    const float* src = g_vT + ((size_t)b * N + n0) * E;
    for (int idx = tid; idx < 4096; idx += 256) {
        int nl = idx >> 6, e = idx & 63;
        as[nl * 68 + e] = src[idx];
    }
    __syncthreads();

    int tx = tid & 63, ty = tid >> 6;
    const float* xcol = x + ((size_t)b * C) * N + n0 + tx;
    float* ycol = y + ((size_t)b * C) * N + n0 + tx;
    const float4* a4 = (const float4*)&as[tx * 68];

    for (int m0 = 0; m0 < 64; m0 += 4) {
        float acc[4] = {0.f, 0.f, 0.f, 0.f};
        #pragma unroll
        for (int e4 = 0; e4 < 16; e4++) {
            float4 a = a4[e4];
            #pragma unroll
            for (int mi = 0; mi < 4; mi++) {
                int c = ty + 4 * (m0 + mi);
                float4 wv = ((const float4*)(ws + c * 64))[e4];
                acc[mi] += a.x * wv.x + a.y * wv.y + a.z * wv.z + a.w * wv.w;
            }
        }
        #pragma unroll
        for (int mi = 0; mi < 4; mi++) {
            int c = ty + 4 * (m0 + mi);
            float o = acc[mi] * 0.125f + b_att[c];
            ycol[(size_t)c * N] = gamma[c] * o + xcol[(size_t)c * N];
        }
    }
}

// ---------------------------------------------------------------------------
extern "C" void kernel_launch(void* const* d_in, const int* in_sizes, int n_in,
                              void* d_out, int out_size)
{
    const float* x  = (const float*)d_in[0];
    const float* wk = (const float*)d_in[1];
    const float* bk = (const float*)d_in[2];
    const float* wq = (const float*)d_in[3];
    const float* bq = (const float*)d_in[4];
    const float* wv = (const float*)d_in[5];
    const float* bv = (const float*)d_in[6];
    const float* wa = (const float*)d_in[7];
    const float* ba = (const float*)d_in[8];
    const float* gm = (const float*)d_in[9];
    float* y = (float*)d_out;

    cudaFuncSetAttribute(proj_kernel, cudaFuncAttributeMaxDynamicSharedMemorySize, 69632);
    cudaFuncSetAttribute(flash_mma,  cudaFuncAttributeMaxDynamicSharedMemorySize, 77824);
    cudaFuncSetAttribute(out_kernel, cudaFuncAttributeMaxDynamicSharedMemorySize, 84000);

    proj_kernel<<<dim3(N / 64, B), 384, 67584>>>(x, wk, bk, wq, bq, wv, bv);
    flash_mma<<<dim3(N / 128, B), 256, 77824>>>();
    out_kernel<<<dim3(N / 64, B), 256, 82944>>>(x, wa, ba, gm, y);
}

// round 12
// speedup vs baseline: 2.5639x; 1.5290x over previous
#include <cuda_runtime.h>
#include <cuda_fp16.h>
#include <math.h>
#include <stdint.h>

static constexpr int B = 8, C = 256, E = 64, N = 4096;

__device__ __half   g_fK[B * N * E];   // key   [b][n][islot_h(e)] fp16
__device__ float    g_gT[B * N * E];   // query [b][n][e] fp32
__device__ __half   g_hV[B * E * N];   // value [b][e][islot_h(n%16)] fp16
__device__ float    g_vT[B * N * E];   // attn out [b][n][e]
__device__ uint32_t g_wh[192 * 128];   // fp16x2 W [r][pair-interleaved c]

// ---------------- helpers ----------------
__device__ __forceinline__ uint32_t smem_u32(const void* p) {
    uint32_t a;
    asm("{ .reg .u64 t; cvta.to.shared.u64 t, %1; cvt.u32.u64 %0, t; }" : "=r"(a) : "l"(p));
    return a;
}
__device__ __forceinline__ void cpasync16(uint32_t dst, const void* src) {
    asm volatile("cp.async.cg.shared.global [%0], [%1], 16;" :: "r"(dst), "l"(src));
}
#define CP_COMMIT() asm volatile("cp.async.commit_group;" ::: "memory")
#define CP_WAIT0()  asm volatile("cp.async.wait_group 0;" ::: "memory")

// pack two f32 -> f16x2 (lo first)
__device__ __forceinline__ uint32_t h2pack(float lo, float hi) {
    uint32_t r;
    asm("cvt.rn.f16x2.f32 %0, %1, %2;" : "=r"(r) : "f"(hi), "f"(lo));
    return r;
}
// interleave within 16-block (half index): pair order [0,4,1,5,2,6,3,7]
__device__ __forceinline__ int islot_h(int e) {
    int c = e & 15, pair = c >> 1;
    int pos = 2 * (pair & 3) + (pair >> 2);
    return (e & ~15) | (pos << 1) | (c & 1);
}
// u32 slot of even element e within interleaved stream
__device__ __forceinline__ int pslot(int e) {
    int p = (e >> 1) & 7;
    return ((e >> 4) << 3) + (((p & 3) << 1) | (p >> 2));
}
// D += A(16x16) * B(16x8), fp16 inputs, fp32 accum
__device__ __forceinline__ void mma16(float* d, const uint32_t* a, uint32_t b0, uint32_t b1) {
    asm volatile(
        "mma.sync.aligned.m16n8k16.row.col.f32.f16.f16.f32 "
        "{%0,%1,%2,%3}, {%4,%5,%6,%7}, {%8,%9}, {%0,%1,%2,%3};"
        : "+f"(d[0]), "+f"(d[1]), "+f"(d[2]), "+f"(d[3])
        : "r"(a[0]), "r"(a[1]), "r"(a[2]), "r"(a[3]), "r"(b0), "r"(b1));
}

// ---------------------------------------------------------------------------
// W pre-pass: fp32 wk/wq/wv [64,256] -> fp16 pair-interleaved g_wh [192][128u32]
// ---------------------------------------------------------------------------
__global__ void w_pre(const float* __restrict__ wk, const float* __restrict__ wq,
                      const float* __restrict__ wv)
{
    int idx = blockIdx.x * 256 + threadIdx.x;   // 0..12287
    int r = idx >> 6, c4 = (idx & 63) << 2;
    const float* wsrc = (r < 64) ? wk + r * 256
                      : (r < 128 ? wq + (r - 64) * 256 : wv + (r - 128) * 256);
    float4 v = *(const float4*)(wsrc + c4);
    int base = r * 128 + ((c4 >> 4) << 3);
    int pb = (c4 >> 1) & 7;         // even pair
    g_wh[base + (((pb & 3) << 1) | (pb >> 2))]   = h2pack(v.x, v.y);
    int pb1 = pb + 1;
    g_wh[base + (((pb1 & 3) << 1) | (pb1 >> 2))] = h2pack(v.z, v.w);
}

// ---------------------------------------------------------------------------
// Projection via mma.sync fp16: D[192 r][64 n] per CTA, k-chunks of 64 (x4).
// A = W fp16 (pre-interleaved, LDS.64 frags); B = x fp32 smem [c][n] pitch 68
// (4x LDS.32 + 2 pack per frag, conflict-free). Double-buffered cp.async.
// Warp grid 4(M) x 2(N); m-frag mi: rows wm*16 + 64*mi -> mi = K/Q/V block.
// grid (N/64=64, B), 256 thr, smem 96256 B, 2 CTAs/SM.
// ---------------------------------------------------------------------------
__global__ __launch_bounds__(256, 2) void proj_kernel(
    const float* __restrict__ x,
    const float* __restrict__ bk, const float* __restrict__ bq,
    const float* __restrict__ bv)
{
    extern __shared__ char ps[];
    __half* Wh = (__half*)ps;                 // 2 bufs x [192][80] halves
    float*  xs = (float*)(ps + 61440);        // 2 bufs x [64][68] f32

    const int b  = blockIdx.y;
    const int n0 = blockIdx.x << 6;
    const int tid = threadIdx.x;
    const int lane = tid & 31, w = tid >> 5;
    const int tig = lane & 3, gid = lane >> 2;
    const int wm = w & 3, wn = w >> 2;
    const float* xb = x + (size_t)b * C * N;

    auto stageW = [&](int kc, int bw) {
        const char* src = (const char*)g_wh;
        #pragma unroll
        for (int k = 0; k < 6; k++) {
            int u = tid + (k << 8);
            int row = u >> 3, c16 = u & 7;
            cpasync16(smem_u32(Wh + bw * 15360 + row * 80 + c16 * 8),
                      src + row * 512 + kc * 128 + c16 * 16);
        }
    };
    auto stageX = [&](int kc, int bw) {
        #pragma unroll
        for (int k = 0; k < 4; k++) {
            int u = tid + (k << 8);
            int crow = u >> 4, nu = u & 15;
            cpasync16(smem_u32(xs + bw * 4352 + crow * 68 + (nu << 2)),
                      xb + (size_t)(kc * 64 + crow) * N + n0 + (nu << 2));
        }
    };

    stageW(0, 0); stageX(0, 0); CP_COMMIT();

    float D[3][4][4];
    #pragma unroll
    for (int mi = 0; mi < 3; mi++)
        #pragma unroll
        for (int ni = 0; ni < 4; ni++)
            #pragma unroll
            for (int i = 0; i < 4; i++) D[mi][ni][i] = 0.f;

    for (int kc = 0; kc < 4; kc++) {
        const int bufc = kc & 1;
        CP_WAIT0();
        __syncthreads();
        if (kc < 3) { stageW(kc + 1, bufc ^ 1); stageX(kc + 1, bufc ^ 1); CP_COMMIT(); }

        const __half* Wc = Wh + bufc * 15360;
        const float*  Xc = xs + bufc * 4352;
        #pragma unroll
        for (int ks = 0; ks < 4; ks++) {
            uint32_t A[3][4];
            #pragma unroll
            for (int mi = 0; mi < 3; mi++) {
                int r1 = wm * 16 + 64 * mi + gid;
                uint2 lo = *(const uint2*)&Wc[r1 * 80 + ks * 16 + tig * 4];
                uint2 hi = *(const uint2*)&Wc[(r1 + 8) * 80 + ks * 16 + tig * 4];
                A[mi][0] = lo.x; A[mi][1] = hi.x; A[mi][2] = lo.y; A[mi][3] = hi.y;
            }
            #pragma unroll
            for (int ni = 0; ni < 4; ni++) {
                int n  = wn * 32 + ni * 8 + gid;
                int cb = ks * 16 + 2 * tig;
                uint32_t b0 = h2pack(Xc[cb * 68 + n],       Xc[(cb + 1) * 68 + n]);
                uint32_t b1 = h2pack(Xc[(cb + 8) * 68 + n], Xc[(cb + 9) * 68 + n]);
                #pragma unroll
                for (int mi = 0; mi < 3; mi++) mma16(D[mi][ni], A[mi], b0, b1);
            }
        }
    }

    // ---- epilogue: scale + bias, emit K fp16-interleaved / Q fp32 / V fp16 ----
    const float sc = 0.0625f;
    const int nb2 = n0 + wn * 32;
    const int e0 = wm * 16 + gid;

    {   // K (mi=0): pairs along e via shfl_xor(4)
        float bk0 = bk[e0], bk8 = bk[e0 + 8];
        uint32_t* Kp = (uint32_t*)g_fK + (size_t)b * N * 32;
        const bool even = (gid & 1) == 0;
        #pragma unroll
        for (int ni = 0; ni < 4; ni++) {
            float c0 = D[0][ni][0] * sc + bk0, c1 = D[0][ni][1] * sc + bk0;
            float c2 = D[0][ni][2] * sc + bk8, c3 = D[0][ni][3] * sc + bk8;
            float p0 = __shfl_xor_sync(0xffffffffu, c0, 4);
            float p1 = __shfl_xor_sync(0xffffffffu, c1, 4);
            float p2 = __shfl_xor_sync(0xffffffffu, c2, 4);
            float p3 = __shfl_xor_sync(0xffffffffu, c3, 4);
            int n = nb2 + ni * 8 + 2 * tig;
            if (even) {
                Kp[(size_t)n * 32 + pslot(e0)]     = h2pack(c0, p0);
                Kp[(size_t)n * 32 + pslot(e0 + 8)] = h2pack(c2, p2);
            } else {
                Kp[(size_t)(n + 1) * 32 + pslot(e0 - 1)] = h2pack(p1, c1);
                Kp[(size_t)(n + 1) * 32 + pslot(e0 + 7)] = h2pack(p3, c3);
            }
        }
    }
    {   // Q (mi=1): fp32 [n][e]
        float bq0 = bq[e0], bq8 = bq[e0 + 8];
        float* Qp = g_gT + (size_t)b * N * 64;
        #pragma unroll
        for (int ni = 0; ni < 4; ni++) {
            int n = nb2 + ni * 8 + 2 * tig;
            Qp[(size_t)n * 64 + e0]           = D[1][ni][0] * sc + bq0;
            Qp[(size_t)(n + 1) * 64 + e0]     = D[1][ni][1] * sc + bq0;
            Qp[(size_t)n * 64 + e0 + 8]       = D[1][ni][2] * sc + bq8;
            Qp[(size_t)(n + 1) * 64 + e0 + 8] = D[1][ni][3] * sc + bq8;
        }
    }
    {   // V (mi=2): pairs along n in-thread
        float bv0 = bv[e0], bv8 = bv[e0 + 8];
        uint32_t* Vp = (uint32_t*)g_hV + (size_t)b * 64 * 2048;
        #pragma unroll
        for (int ni = 0; ni < 4; ni++) {
            int n = nb2 + ni * 8 + 2 * tig;
            int slot = pslot(n);
            Vp[(size_t)e0 * 2048 + slot]       = h2pack(D[2][ni][0] * sc + bv0,
                                                        D[2][ni][1] * sc + bv0);
            Vp[(size_t)(e0 + 8) * 2048 + slot] = h2pack(D[2][ni][2] * sc + bv8,
                                                        D[2][ni][3] * sc + bv8);
        }
    }
}

// ---------------------------------------------------------------------------
// Flash attention, mma.sync fp16 m16n8k16 (fp32 accum). P in registers.
// (unchanged from R10 — known-good at 354 µs)
// ---------------------------------------------------------------------------
static constexpr int KHALF = 5120;
static constexpr int NT = N / 64;

__global__ __launch_bounds__(256, 2) void flash_mma()
{
    extern __shared__ char sraw[];
    __half* Ks = (__half*)sraw;
    __half* Vs = (__half*)(sraw + 20480);
    float*  Psm = (float*)(sraw + 40960);

    const int tid = threadIdx.x;
    const int lane = tid & 31, w = tid >> 5;
    const int tig = lane & 3, gid = lane >> 2;
    const int b = blockIdx.y, q0 = blockIdx.x << 7;

    const __half* Kg = g_fK + (size_t)b * N * E;
    const __half* Vg = g_hV + (size_t)b * E * N;
    const float*  Qg = g_gT + ((size_t)b * N + q0) * E;

    const int srow = tid >> 3, schunk = (tid & 7) << 3;

    for (int i = tid; i < 2048; i += 256) {
        int row = i >> 4, c4 = (i & 15) << 2;
        cpasync16(smem_u32(Psm + row * 72 + c4), Qg + row * 64 + c4);
    }
    #pragma unroll
    for (int p = 0; p < 2; p++) {
        int row = srow + 32 * p;
        cpasync16(smem_u32(Ks + row * 80 + schunk), Kg + (size_t)row * 64 + schunk);
        cpasync16(smem_u32(Vs + row * 80 + schunk), Vg + (size_t)row * N + schunk);
    }
    CP_COMMIT();
    CP_WAIT0();
    __syncthreads();

    uint32_t qa[4][4];
    {
        const float* Qs = Psm + (w * 16) * 72;
        #pragma unroll
        for (int ks = 0; ks < 4; ks++) {
            int e0 = 16 * ks + 2 * tig;
            qa[ks][0] = h2pack(Qs[gid * 72 + e0],           Qs[gid * 72 + e0 + 1]);
            qa[ks][1] = h2pack(Qs[(gid + 8) * 72 + e0],     Qs[(gid + 8) * 72 + e0 + 1]);
            qa[ks][2] = h2pack(Qs[gid * 72 + e0 + 8],       Qs[gid * 72 + e0 + 9]);
            qa[ks][3] = h2pack(Qs[(gid + 8) * 72 + e0 + 8], Qs[(gid + 8) * 72 + e0 + 9]);
        }
    }
    __syncthreads();

    float O[8][4];
    #pragma unroll
    for (int j = 0; j < 8; j++)
        #pragma unroll
        for (int i = 0; i < 4; i++) O[j][i] = 0.f;
    float m0 = -1e30f, m1 = -1e30f, l0 = 0.f, l1 = 0.f;

    for (int t = 0; t < NT; ++t) {
        const int buf = t & 1, nb = buf ^ 1;
        const bool pref = (t < NT - 1);
        const int k0n = (t + 1) << 6;

        if (pref) {
            #pragma unroll
            for (int p = 0; p < 2; p++) {
                int row = srow + 32 * p;
                cpasync16(smem_u32(Ks + nb * KHALF + row * 80 + schunk),
                          Kg + (size_t)(k0n + row) * 64 + schunk);
                cpasync16(smem_u32(Vs + nb * KHALF + row * 80 + schunk),
                          Vg + (size_t)row * N + k0n + schunk);
            }
            CP_COMMIT();
        }

        float S[8][4];
        #pragma unroll
        for (int j = 0; j < 8; j++)
            #pragma unroll
            for (int i = 0; i < 4; i++) S[j][i] = 0.f;
        {
            const __half* Kh = Ks + buf * KHALF;
            #pragma unroll
            for (int ks = 0; ks < 4; ks++) {
                int off = ks * 16 + tig * 4;
                #pragma unroll
                for (int j = 0; j < 8; j++) {
                    uint2 bb = *(const uint2*)&Kh[(gid + 8 * j) * 80 + off];
                    mma16(S[j], qa[ks], bb.x, bb.y);
                }
            }
        }

        float c0m = -1e30f, c1m = -1e30f;
        #pragma unroll
        for (int j = 0; j < 8; j++) {
            c0m = fmaxf(c0m, fmaxf(S[j][0], S[j][1]));
            c1m = fmaxf(c1m, fmaxf(S[j][2], S[j][3]));
        }
        c0m = fmaxf(c0m, __shfl_xor_sync(0xffffffffu, c0m, 1));
        c0m = fmaxf(c0m, __shfl_xor_sync(0xffffffffu, c0m, 2));
        c1m = fmaxf(c1m, __shfl_xor_sync(0xffffffffu, c1m, 1));
        c1m = fmaxf(c1m, __shfl_xor_sync(0xffffffffu, c1m, 2));
        float mn0 = fmaxf(m0, c0m), mn1 = fmaxf(m1, c1m);
        bool need = (mn0 > m0) || (mn1 > m1);
        float a0 = __expf(m0 - mn0), a1 = __expf(m1 - mn1);
        m0 = mn0; m1 = mn1;

        float s0 = 0.f, s1 = 0.f;
        #pragma unroll
        for (int j = 0; j < 8; j++) {
            S[j][0] = __expf(S[j][0] - m0); S[j][1] = __expf(S[j][1] - m0);
            S[j][2] = __expf(S[j][2] - m1); S[j][3] = __expf(S[j][3] - m1);
            s0 += S[j][0] + S[j][1];
            s1 += S[j][2] + S[j][3];
        }
        s0 += __shfl_xor_sync(0xffffffffu, s0, 1);
        s0 += __shfl_xor_sync(0xffffffffu, s0, 2);
        s1 += __shfl_xor_sync(0xffffffffu, s1, 1);
        s1 += __shfl_xor_sync(0xffffffffu, s1, 2);
        l0 = l0 * a0 + s0;
        l1 = l1 * a1 + s1;
        if (__any_sync(0xffffffffu, need)) {
            #pragma unroll
            for (int j = 0; j < 8; j++) {
                O[j][0] *= a0; O[j][1] *= a0; O[j][2] *= a1; O[j][3] *= a1;
            }
        }

        {
            const __half* Vh = Vs + buf * KHALF;
            #pragma unroll
            for (int m = 0; m < 4; m++) {
                uint32_t pa[4] = {
                    h2pack(S[2 * m][0],     S[2 * m][1]),
                    h2pack(S[2 * m][2],     S[2 * m][3]),
                    h2pack(S[2 * m + 1][0], S[2 * m + 1][1]),
                    h2pack(S[2 * m + 1][2], S[2 * m + 1][3])
                };
                int off = m * 16 + tig * 4;
                #pragma unroll
                for (int j = 0; j < 8; j++) {
                    uint2 vv = *(const uint2*)&Vh[(gid + 8 * j) * 80 + off];
                    mma16(O[j], pa, vv.x, vv.y);
                }
            }
        }

        CP_WAIT0();
        __syncthreads();
    }

    {
        const int r0 = w * 16 + gid;
        float* rp  = Psm + r0 * 72;
        float* rp8 = rp + 8 * 72;
        float i0 = 1.f / l0, i1 = 1.f / l1;
        #pragma unroll
        for (int j = 0; j < 8; j++) {
            int col = 8 * j + 2 * tig;
            *(float2*)&rp[col]  = make_float2(O[j][0] * i0, O[j][1] * i0);
            *(float2*)&rp8[col] = make_float2(O[j][2] * i1, O[j][3] * i1);
        }
    }
    __syncthreads();
    {
        float* dst = g_vT + ((size_t)b * N + q0) * E;
        for (int i = tid; i < 2048; i += 256) {
            int row = i >> 4, c4 = (i & 15) << 2;
            *(float4*)(dst + (size_t)row * 64 + c4) = *(float4*)(Psm + row * 72 + c4);
        }
    }
}

// ---------------------------------------------------------------------------
// Output: y = gamma * (w_att @ v / 8 + b_att) + x   (unchanged, known-good)
// ---------------------------------------------------------------------------
__global__ __launch_bounds__(256) void out_kernel(
    const float* __restrict__ x, const float* __restrict__ w_att,
    const float* __restrict__ b_att, const float* __restrict__ gamma,
    float* __restrict__ y)
{
    extern __shared__ float sm[];
    float* ws = sm;               // [256][64]
    float* as = sm + 256 * 64;    // [64][68]
    int b = blockIdx.y, n0 = blockIdx.x << 6;
    int tid = threadIdx.x;

    float4* ws4 = (float4*)ws;
    const float4* wg4 = (const float4*)w_att;
    for (int idx = tid; idx < 4096; idx += 256) ws4[idx] = wg4[idx];
    const float* src = g_vT + ((size_t)b * N + n0) * E;
    for (int idx = tid; idx < 4096; idx += 256) {
        int nl = idx >> 6, e = idx & 63;
        as[nl * 68 + e] = src[idx];
    }
    __syncthreads();

    int tx = tid & 63, ty = tid >> 6;
    const float* xcol = x + ((size_t)b * C) * N + n0 + tx;
    float* ycol = y + ((size_t)b * C) * N + n0 + tx;
    const float4* a4 = (const float4*)&as[tx * 68];

    for (int m0 = 0; m0 < 64; m0 += 4) {
        float acc[4] = {0.f, 0.f, 0.f, 0.f};
        #pragma unroll
        for (int e4 = 0; e4 < 16; e4++) {
            float4 a = a4[e4];
            #pragma unroll
            for (int mi = 0; mi < 4; mi++) {
                int c = ty + 4 * (m0 + mi);
                float4 wv = ((const float4*)(ws + c * 64))[e4];
                acc[mi] += a.x * wv.x + a.y * wv.y + a.z * wv.z + a.w * wv.w;
            }
        }
        #pragma unroll
        for (int mi = 0; mi < 4; mi++) {
            int c = ty + 4 * (m0 + mi);
            float o = acc[mi] * 0.125f + b_att[c];
            ycol[(size_t)c * N] = gamma[c] * o + xcol[(size_t)c * N];
        }
    }
}

// ---------------------------------------------------------------------------
extern "C" void kernel_launch(void* const* d_in, const int* in_sizes, int n_in,
                              void* d_out, int out_size)
{
    const float* x  = (const float*)d_in[0];
    const float* wk = (const float*)d_in[1];
    const float* bk = (const float*)d_in[2];
    const float* wq = (const float*)d_in[3];
    const float* bq = (const float*)d_in[4];
    const float* wv = (const float*)d_in[5];
    const float* bv = (const float*)d_in[6];
    const float* wa = (const float*)d_in[7];
    const float* ba = (const float*)d_in[8];
    const float* gm = (const float*)d_in[9];
    float* y = (float*)d_out;

    cudaFuncSetAttribute(proj_kernel, cudaFuncAttributeMaxDynamicSharedMemorySize, 98304);
    cudaFuncSetAttribute(flash_mma,  cudaFuncAttributeMaxDynamicSharedMemorySize, 77824);
    cudaFuncSetAttribute(out_kernel, cudaFuncAttributeMaxDynamicSharedMemorySize, 84000);

    w_pre<<<48, 256>>>(wk, wq, wv);
    proj_kernel<<<dim3(N / 64, B), 256, 96256>>>(x, bk, bq, bv);
    flash_mma<<<dim3(N / 128, B), 256, 77824>>>();
    out_kernel<<<dim3(N / 64, B), 256, 82944>>>(x, wa, ba, gm, y);
}

// round 14
// speedup vs baseline: 3.2245x; 1.2576x over previous
#include <cuda_runtime.h>
#include <cuda_fp16.h>
#include <math.h>
#include <stdint.h>

static constexpr int B = 8, C = 256, E = 64, N = 4096;

__device__ __half   g_fK[B * N * E];   // key   [b][n][islot_h(e)] fp16
__device__ float    g_gT[B * N * E];   // query [b][n][e] fp32
__device__ __half   g_hV[B * E * N];   // value [b][e][islot_h(n%16)] fp16
__device__ __half   g_oH[B * N * E];   // attn out [b][n][islot_h(e)] fp16
__device__ uint32_t g_wh[192 * 128];   // fp16x2 W(kqv) [r][pair-interleaved c]
__device__ uint32_t g_waH[256 * 32];   // fp16x2 w_att [c][pair-interleaved e]

// ---------------- helpers ----------------
__device__ __forceinline__ uint32_t smem_u32(const void* p) {
    uint32_t a;
    asm("{ .reg .u64 t; cvta.to.shared.u64 t, %1; cvt.u32.u64 %0, t; }" : "=r"(a) : "l"(p));
    return a;
}
__device__ __forceinline__ void cpasync16(uint32_t dst, const void* src) {
    asm volatile("cp.async.cg.shared.global [%0], [%1], 16;" :: "r"(dst), "l"(src));
}
#define CP_COMMIT() asm volatile("cp.async.commit_group;" ::: "memory")
#define CP_WAIT0()  asm volatile("cp.async.wait_group 0;" ::: "memory")

__device__ __forceinline__ uint32_t h2pack(float lo, float hi) {
    uint32_t r;
    asm("cvt.rn.f16x2.f32 %0, %1, %2;" : "=r"(r) : "f"(hi), "f"(lo));
    return r;
}
// u32 slot of even element e within pair-interleaved stream
__device__ __forceinline__ int pslot(int e) {
    int p = (e >> 1) & 7;
    return ((e >> 4) << 3) + (((p & 3) << 1) | (p >> 2));
}
// D += A(16x16) * B(16x8), fp16 inputs, fp32 accum
__device__ __forceinline__ void mma16(float* d, const uint32_t* a, uint32_t b0, uint32_t b1) {
    asm volatile(
        "mma.sync.aligned.m16n8k16.row.col.f32.f16.f16.f32 "
        "{%0,%1,%2,%3}, {%4,%5,%6,%7}, {%8,%9}, {%0,%1,%2,%3};"
        : "+f"(d[0]), "+f"(d[1]), "+f"(d[2]), "+f"(d[3])
        : "r"(a[0]), "r"(a[1]), "r"(a[2]), "r"(a[3]), "r"(b0), "r"(b1));
}

// ---------------------------------------------------------------------------
// W pre-pass: wk/wq/wv -> g_wh (pair-interleaved per 16-block of c);
//             w_att [256][64] -> g_waH [c][pair-interleaved e].
// ---------------------------------------------------------------------------
__global__ void w_pre(const float* __restrict__ wk, const float* __restrict__ wq,
                      const float* __restrict__ wv, const float* __restrict__ wa)
{
    int idx = blockIdx.x * 256 + threadIdx.x;   // 0..16383
    if (idx < 12288) {
        int r = idx >> 6, c4 = (idx & 63) << 2;
        const float* wsrc = (r < 64) ? wk + r * 256
                          : (r < 128 ? wq + (r - 64) * 256 : wv + (r - 128) * 256);
        float4 v = *(const float4*)(wsrc + c4);
        int base = r * 128 + ((c4 >> 4) << 3);
        int pb = (c4 >> 1) & 7;
        g_wh[base + (((pb & 3) << 1) | (pb >> 2))]   = h2pack(v.x, v.y);
        int pb1 = pb + 1;
        g_wh[base + (((pb1 & 3) << 1) | (pb1 >> 2))] = h2pack(v.z, v.w);
    } else {
        int i2 = idx - 12288;                   // 0..4095
        int r = i2 >> 4, c4 = (i2 & 15) << 2;   // r: c-row 0..255, c4: e 0,4,..60
        float4 v = *(const float4*)(wa + r * 64 + c4);
        int base = r * 32 + ((c4 >> 4) << 3);
        int pb = (c4 >> 1) & 7;
        g_waH[base + (((pb & 3) << 1) | (pb >> 2))]   = h2pack(v.x, v.y);
        int pb1 = pb + 1;
        g_waH[base + (((pb1 & 3) << 1) | (pb1 >> 2))] = h2pack(v.z, v.w);
    }
}

// ---------------------------------------------------------------------------
// Projection via mma.sync fp16  (unchanged from R12 — known-good)
// ---------------------------------------------------------------------------
__global__ __launch_bounds__(256, 2) void proj_kernel(
    const float* __restrict__ x,
    const float* __restrict__ bk, const float* __restrict__ bq,
    const float* __restrict__ bv)
{
    extern __shared__ char ps[];
    __half* Wh = (__half*)ps;                 // 2 bufs x [192][80] halves
    float*  xs = (float*)(ps + 61440);        // 2 bufs x [64][68] f32

    const int b  = blockIdx.y;
    const int n0 = blockIdx.x << 6;
    const int tid = threadIdx.x;
    const int lane = tid & 31, w = tid >> 5;
    const int tig = lane & 3, gid = lane >> 2;
    const int wm = w & 3, wn = w >> 2;
    const float* xb = x + (size_t)b * C * N;

    auto stageW = [&](int kc, int bw) {
        const char* src = (const char*)g_wh;
        #pragma unroll
        for (int k = 0; k < 6; k++) {
            int u = tid + (k << 8);
            int row = u >> 3, c16 = u & 7;
            cpasync16(smem_u32(Wh + bw * 15360 + row * 80 + c16 * 8),
                      src + row * 512 + kc * 128 + c16 * 16);
        }
    };
    auto stageX = [&](int kc, int bw) {
        #pragma unroll
        for (int k = 0; k < 4; k++) {
            int u = tid + (k << 8);
            int crow = u >> 4, nu = u & 15;
            cpasync16(smem_u32(xs + bw * 4352 + crow * 68 + (nu << 2)),
                      xb + (size_t)(kc * 64 + crow) * N + n0 + (nu << 2));
        }
    };

    stageW(0, 0); stageX(0, 0); CP_COMMIT();

    float D[3][4][4];
    #pragma unroll
    for (int mi = 0; mi < 3; mi++)
        #pragma unroll
        for (int ni = 0; ni < 4; ni++)
            #pragma unroll
            for (int i = 0; i < 4; i++) D[mi][ni][i] = 0.f;

    for (int kc = 0; kc < 4; kc++) {
        const int bufc = kc & 1;
        CP_WAIT0();
        __syncthreads();
        if (kc < 3) { stageW(kc + 1, bufc ^ 1); stageX(kc + 1, bufc ^ 1); CP_COMMIT(); }

        const __half* Wc = Wh + bufc * 15360;
        const float*  Xc = xs + bufc * 4352;
        #pragma unroll
        for (int ks = 0; ks < 4; ks++) {
            uint32_t A[3][4];
            #pragma unroll
            for (int mi = 0; mi < 3; mi++) {
                int r1 = wm * 16 + 64 * mi + gid;
                uint2 lo = *(const uint2*)&Wc[r1 * 80 + ks * 16 + tig * 4];
                uint2 hi = *(const uint2*)&Wc[(r1 + 8) * 80 + ks * 16 + tig * 4];
                A[mi][0] = lo.x; A[mi][1] = hi.x; A[mi][2] = lo.y; A[mi][3] = hi.y;
            }
            #pragma unroll
            for (int ni = 0; ni < 4; ni++) {
                int n  = wn * 32 + ni * 8 + gid;
                int cb = ks * 16 + 2 * tig;
                uint32_t b0 = h2pack(Xc[cb * 68 + n],       Xc[(cb + 1) * 68 + n]);
                uint32_t b1 = h2pack(Xc[(cb + 8) * 68 + n], Xc[(cb + 9) * 68 + n]);
                #pragma unroll
                for (int mi = 0; mi < 3; mi++) mma16(D[mi][ni], A[mi], b0, b1);
            }
        }
    }

    const float sc = 0.0625f;
    const int nb2 = n0 + wn * 32;
    const int e0 = wm * 16 + gid;

    {   // K (mi=0): pairs along e via shfl_xor(4)
        float bk0 = bk[e0], bk8 = bk[e0 + 8];
        uint32_t* Kp = (uint32_t*)g_fK + (size_t)b * N * 32;
        const bool even = (gid & 1) == 0;
        #pragma unroll
        for (int ni = 0; ni < 4; ni++) {
            float c0 = D[0][ni][0] * sc + bk0, c1 = D[0][ni][1] * sc + bk0;
            float c2 = D[0][ni][2] * sc + bk8, c3 = D[0][ni][3] * sc + bk8;
            float p0 = __shfl_xor_sync(0xffffffffu, c0, 4);
            float p1 = __shfl_xor_sync(0xffffffffu, c1, 4);
            float p2 = __shfl_xor_sync(0xffffffffu, c2, 4);
            float p3 = __shfl_xor_sync(0xffffffffu, c3, 4);
            int n = nb2 + ni * 8 + 2 * tig;
            if (even) {
                Kp[(size_t)n * 32 + pslot(e0)]     = h2pack(c0, p0);
                Kp[(size_t)n * 32 + pslot(e0 + 8)] = h2pack(c2, p2);
            } else {
                Kp[(size_t)(n + 1) * 32 + pslot(e0 - 1)] = h2pack(p1, c1);
                Kp[(size_t)(n + 1) * 32 + pslot(e0 + 7)] = h2pack(p3, c3);
            }
        }
    }
    {   // Q (mi=1): fp32 [n][e]
        float bq0 = bq[e0], bq8 = bq[e0 + 8];
        float* Qp = g_gT + (size_t)b * N * 64;
        #pragma unroll
        for (int ni = 0; ni < 4; ni++) {
            int n = nb2 + ni * 8 + 2 * tig;
            Qp[(size_t)n * 64 + e0]           = D[1][ni][0] * sc + bq0;
            Qp[(size_t)(n + 1) * 64 + e0]     = D[1][ni][1] * sc + bq0;
            Qp[(size_t)n * 64 + e0 + 8]       = D[1][ni][2] * sc + bq8;
            Qp[(size_t)(n + 1) * 64 + e0 + 8] = D[1][ni][3] * sc + bq8;
        }
    }
    {   // V (mi=2): pairs along n in-thread
        float bv0 = bv[e0], bv8 = bv[e0 + 8];
        uint32_t* Vp = (uint32_t*)g_hV + (size_t)b * 64 * 2048;
        #pragma unroll
        for (int ni = 0; ni < 4; ni++) {
            int n = nb2 + ni * 8 + 2 * tig;
            int slot = pslot(n);
            Vp[(size_t)e0 * 2048 + slot]       = h2pack(D[2][ni][0] * sc + bv0,
                                                        D[2][ni][1] * sc + bv0);
            Vp[(size_t)(e0 + 8) * 2048 + slot] = h2pack(D[2][ni][2] * sc + bv8,
                                                        D[2][ni][3] * sc + bv8);
        }
    }
}

// ---------------------------------------------------------------------------
// Flash attention, mma.sync fp16 (unchanged core); epilogue emits O as
// fp16 [n][islot(e)] directly from registers (pairs are in-thread).
// ---------------------------------------------------------------------------
static constexpr int KHALF = 5120;
static constexpr int NT = N / 64;

__global__ __launch_bounds__(256, 2) void flash_mma()
{
    extern __shared__ char sraw[];
    __half* Ks = (__half*)sraw;
    __half* Vs = (__half*)(sraw + 20480);
    float*  Psm = (float*)(sraw + 40960);

    const int tid = threadIdx.x;
    const int lane = tid & 31, w = tid >> 5;
    const int tig = lane & 3, gid = lane >> 2;
    const int b = blockIdx.y, q0 = blockIdx.x << 7;

    const __half* Kg = g_fK + (size_t)b * N * E;
    const __half* Vg = g_hV + (size_t)b * E * N;
    const float*  Qg = g_gT + ((size_t)b * N + q0) * E;

    const int srow = tid >> 3, schunk = (tid & 7) << 3;

    for (int i = tid; i < 2048; i += 256) {
        int row = i >> 4, c4 = (i & 15) << 2;
        cpasync16(smem_u32(Psm + row * 72 + c4), Qg + row * 64 + c4);
    }
    #pragma unroll
    for (int p = 0; p < 2; p++) {
        int row = srow + 32 * p;
        cpasync16(smem_u32(Ks + row * 80 + schunk), Kg + (size_t)row * 64 + schunk);
        cpasync16(smem_u32(Vs + row * 80 + schunk), Vg + (size_t)row * N + schunk);
    }
    CP_COMMIT();
    CP_WAIT0();
    __syncthreads();

    uint32_t qa[4][4];
    {
        const float* Qs = Psm + (w * 16) * 72;
        #pragma unroll
        for (int ks = 0; ks < 4; ks++) {
            int e0 = 16 * ks + 2 * tig;
            qa[ks][0] = h2pack(Qs[gid * 72 + e0],           Qs[gid * 72 + e0 + 1]);
            qa[ks][1] = h2pack(Qs[(gid + 8) * 72 + e0],     Qs[(gid + 8) * 72 + e0 + 1]);
            qa[ks][2] = h2pack(Qs[gid * 72 + e0 + 8],       Qs[gid * 72 + e0 + 9]);
            qa[ks][3] = h2pack(Qs[(gid + 8) * 72 + e0 + 8], Qs[(gid + 8) * 72 + e0 + 9]);
        }
    }
    __syncthreads();

    float O[8][4];
    #pragma unroll
    for (int j = 0; j < 8; j++)
        #pragma unroll
        for (int i = 0; i < 4; i++) O[j][i] = 0.f;
    float m0 = -1e30f, m1 = -1e30f, l0 = 0.f, l1 = 0.f;

    for (int t = 0; t < NT; ++t) {
        const int buf = t & 1, nb = buf ^ 1;
        const bool pref = (t < NT - 1);
        const int k0n = (t + 1) << 6;

        if (pref) {
            #pragma unroll
            for (int p = 0; p < 2; p++) {
                int row = srow + 32 * p;
                cpasync16(smem_u32(Ks + nb * KHALF + row * 80 + schunk),
                          Kg + (size_t)(k0n + row) * 64 + schunk);
                cpasync16(smem_u32(Vs + nb * KHALF + row * 80 + schunk),
                          Vg + (size_t)row * N + k0n + schunk);
            }
            CP_COMMIT();
        }

        float S[8][4];
        #pragma unroll
        for (int j = 0; j < 8; j++)
            #pragma unroll
            for (int i = 0; i < 4; i++) S[j][i] = 0.f;
        {
            const __half* Kh = Ks + buf * KHALF;
            #pragma unroll
            for (int ks = 0; ks < 4; ks++) {
                int off = ks * 16 + tig * 4;
                #pragma unroll
                for (int j = 0; j < 8; j++) {
                    uint2 bb = *(const uint2*)&Kh[(gid + 8 * j) * 80 + off];
                    mma16(S[j], qa[ks], bb.x, bb.y);
                }
            }
        }

        float c0m = -1e30f, c1m = -1e30f;
        #pragma unroll
        for (int j = 0; j < 8; j++) {
            c0m = fmaxf(c0m, fmaxf(S[j][0], S[j][1]));
            c1m = fmaxf(c1m, fmaxf(S[j][2], S[j][3]));
        }
        c0m = fmaxf(c0m, __shfl_xor_sync(0xffffffffu, c0m, 1));
        c0m = fmaxf(c0m, __shfl_xor_sync(0xffffffffu, c0m, 2));
        c1m = fmaxf(c1m, __shfl_xor_sync(0xffffffffu, c1m, 1));
        c1m = fmaxf(c1m, __shfl_xor_sync(0xffffffffu, c1m, 2));
        float mn0 = fmaxf(m0, c0m), mn1 = fmaxf(m1, c1m);
        bool need = (mn0 > m0) || (mn1 > m1);
        float a0 = __expf(m0 - mn0), a1 = __expf(m1 - mn1);
        m0 = mn0; m1 = mn1;

        float s0 = 0.f, s1 = 0.f;
        #pragma unroll
        for (int j = 0; j < 8; j++) {
            S[j][0] = __expf(S[j][0] - m0); S[j][1] = __expf(S[j][1] - m0);
            S[j][2] = __expf(S[j][2] - m1); S[j][3] = __expf(S[j][3] - m1);
            s0 += S[j][0] + S[j][1];
            s1 += S[j][2] + S[j][3];
        }
        s0 += __shfl_xor_sync(0xffffffffu, s0, 1);
        s0 += __shfl_xor_sync(0xffffffffu, s0, 2);
        s1 += __shfl_xor_sync(0xffffffffu, s1, 1);
        s1 += __shfl_xor_sync(0xffffffffu, s1, 2);
        l0 = l0 * a0 + s0;
        l1 = l1 * a1 + s1;
        if (__any_sync(0xffffffffu, need)) {
            #pragma unroll
            for (int j = 0; j < 8; j++) {
                O[j][0] *= a0; O[j][1] *= a0; O[j][2] *= a1; O[j][3] *= a1;
            }
        }

        {
            const __half* Vh = Vs + buf * KHALF;
            #pragma unroll
            for (int m = 0; m < 4; m++) {
                uint32_t pa[4] = {
                    h2pack(S[2 * m][0],     S[2 * m][1]),
                    h2pack(S[2 * m][2],     S[2 * m][3]),
                    h2pack(S[2 * m + 1][0], S[2 * m + 1][1]),
                    h2pack(S[2 * m + 1][2], S[2 * m + 1][3])
                };
                int off = m * 16 + tig * 4;
                #pragma unroll
                for (int j = 0; j < 8; j++) {
                    uint2 vv = *(const uint2*)&Vh[(gid + 8 * j) * 80 + off];
                    mma16(O[j], pa, vv.x, vv.y);
                }
            }
        }

        CP_WAIT0();
        __syncthreads();
    }

    // epilogue: O/l -> fp16 interleaved, direct stores (pairs in-thread)
    {
        const int r0 = w * 16 + gid;
        float i0 = 1.f / l0, i1 = 1.f / l1;
        uint32_t* Op = (uint32_t*)g_oH + ((size_t)b * N + q0) * 32;
        #pragma unroll
        for (int j = 0; j < 8; j++) {
            int slot = pslot(8 * j + 2 * tig);
            Op[(size_t)r0 * 32 + slot]       = h2pack(O[j][0] * i0, O[j][1] * i0);
            Op[(size_t)(r0 + 8) * 32 + slot] = h2pack(O[j][2] * i1, O[j][3] * i1);
        }
    }
}

// ---------------------------------------------------------------------------
// Output via mma.sync fp16: D[n][c] = o[n][e] x w_att[c][e]^T per 64-n tile.
// A = o (interleaved, LDS.64 frags), B = w_att (interleaved, LDS.64 frags).
// Epilogue: two c-half passes through smem, coalesced float4 y = gamma*o + x.
// grid (N/64, B), 256 thr, smem 86016 B, 2 CTAs/SM.
// ---------------------------------------------------------------------------
__global__ __launch_bounds__(256, 2) void out_kernel(
    const float* __restrict__ x, const float* __restrict__ b_att,
    const float* __restrict__ gamma, float* __restrict__ y)
{
    extern __shared__ char os[];
    __half* Wc = (__half*)os;             // [256][80]h  40960 B
    __half* Ot = (__half*)(os + 40960);   // [64][80]h   10240 B
    float*  Yt = (float*)(os + 51200);    // [128][68]f  34816 B

    const int b = blockIdx.y, n0 = blockIdx.x << 6;
    const int tid = threadIdx.x;
    const int lane = tid & 31, w = tid >> 5;
    const int tig = lane & 3, gid = lane >> 2;
    const int wm = w & 3, wc = w >> 2;    // wm: n-block of 16, wc: c-half of 128

    // stage w_att (interleaved fp16) and o tile
    #pragma unroll
    for (int k = 0; k < 8; k++) {
        int u = tid + (k << 8);
        int row = u >> 3, c16 = u & 7;
        cpasync16(smem_u32(Wc + row * 80 + c16 * 8),
                  (const char*)g_waH + row * 128 + c16 * 16);
    }
    #pragma unroll
    for (int k = 0; k < 2; k++) {
        int u = tid + (k << 8);
        int row = u >> 3, c16 = u & 7;
        cpasync16(smem_u32(Ot + row * 80 + c16 * 8),
                  g_oH + ((size_t)b * N + n0 + row) * 64 + c16 * 8);
    }
    CP_COMMIT();
    CP_WAIT0();
    __syncthreads();

    // A frags from o rows
    uint32_t A[4][4];
    #pragma unroll
    for (int ks = 0; ks < 4; ks++) {
        uint2 lo = *(const uint2*)&Ot[(wm * 16 + gid) * 80 + ks * 16 + tig * 4];
        uint2 hi = *(const uint2*)&Ot[(wm * 16 + gid + 8) * 80 + ks * 16 + tig * 4];
        A[ks][0] = lo.x; A[ks][1] = hi.x; A[ks][2] = lo.y; A[ks][3] = hi.y;
    }

    float Dd[16][4];
    #pragma unroll
    for (int cj = 0; cj < 16; cj++)
        #pragma unroll
        for (int i = 0; i < 4; i++) Dd[cj][i] = 0.f;

    #pragma unroll
    for (int ks = 0; ks < 4; ks++) {
        int off = ks * 16 + tig * 4;
        #pragma unroll
        for (int cj = 0; cj < 16; cj++) {
            uint2 bb = *(const uint2*)&Wc[(wc * 128 + cj * 8 + gid) * 80 + off];
            mma16(Dd[cj], A[ks], bb.x, bb.y);
        }
    }

    // two c-half passes: stage D^T into Yt, stream y = gamma*(D/8+b)+x
    #pragma unroll
    for (int half = 0; half < 2; half++) {
        if (wc == half) {
            #pragma unroll
            for (int cj = 0; cj < 16; cj++) {
                int cl = cj * 8 + 2 * tig;        // local c within half
                int nr = wm * 16 + gid;
                Yt[cl * 68 + nr]           = Dd[cj][0];
                Yt[(cl + 1) * 68 + nr]     = Dd[cj][1];
                Yt[cl * 68 + nr + 8]       = Dd[cj][2];
                Yt[(cl + 1) * 68 + nr + 8] = Dd[cj][3];
            }
        }
        __syncthreads();
        for (int u = tid; u < 2048; u += 256) {
            int cr = u >> 4, n4 = (u & 15) << 2;
            int c = half * 128 + cr;
            float4 o4 = *(const float4*)&Yt[cr * 68 + n4];
            float ba = b_att[c], gm = gamma[c];
            size_t gidx = ((size_t)b * C + c) * N + n0 + n4;
            float4 x4 = *(const float4*)(x + gidx);
            float4 y4;
            y4.x = gm * (o4.x * 0.125f + ba) + x4.x;
            y4.y = gm * (o4.y * 0.125f + ba) + x4.y;
            y4.z = gm * (o4.z * 0.125f + ba) + x4.z;
            y4.w = gm * (o4.w * 0.125f + ba) + x4.w;
            *(float4*)(y + gidx) = y4;
        }
        __syncthreads();
    }
}

// ---------------------------------------------------------------------------
extern "C" void kernel_launch(void* const* d_in, const int* in_sizes, int n_in,
                              void* d_out, int out_size)
{
    const float* x  = (const float*)d_in[0];
    const float* wk = (const float*)d_in[1];
    const float* bk = (const float*)d_in[2];
    const float* wq = (const float*)d_in[3];
    const float* bq = (const float*)d_in[4];
    const float* wv = (const float*)d_in[5];
    const float* bv = (const float*)d_in[6];
    const float* wa = (const float*)d_in[7];
    const float* ba = (const float*)d_in[8];
    const float* gm = (const float*)d_in[9];
    float* y = (float*)d_out;

    cudaFuncSetAttribute(proj_kernel, cudaFuncAttributeMaxDynamicSharedMemorySize, 98304);
    cudaFuncSetAttribute(flash_mma,  cudaFuncAttributeMaxDynamicSharedMemorySize, 77824);
    cudaFuncSetAttribute(out_kernel, cudaFuncAttributeMaxDynamicSharedMemorySize, 90112);

    w_pre<<<64, 256>>>(wk, wq, wv, wa);
    proj_kernel<<<dim3(N / 64, B), 256, 96256>>>(x, bk, bq, bv);
    flash_mma<<<dim3(N / 128, B), 256, 77824>>>();
    out_kernel<<<dim3(N / 64, B), 256, 86016>>>(x, ba, gm, y);
}

// round 15
// speedup vs baseline: 3.3237x; 1.0308x over previous
#include <cuda_runtime.h>
#include <cuda_fp16.h>
#include <math.h>
#include <stdint.h>

static constexpr int B = 8, C = 256, E = 64, N = 4096;

__device__ __half   g_fK[B * N * E];   // key   [b][n][islot_h(e)] fp16
__device__ float    g_gT[B * N * E];   // query [b][n][e] fp32
__device__ __half   g_hV[B * E * N];   // value [b][e][islot_h(n%16)] fp16
__device__ uint32_t g_wh[192 * 128];   // fp16x2 W(kqv) [r][pair-interleaved c]
__device__ uint32_t g_waH[256 * 32];   // fp16x2 w_att [c][pair-interleaved e]

// ---------------- helpers ----------------
__device__ __forceinline__ uint32_t smem_u32(const void* p) {
    uint32_t a;
    asm("{ .reg .u64 t; cvta.to.shared.u64 t, %1; cvt.u32.u64 %0, t; }" : "=r"(a) : "l"(p));
    return a;
}
__device__ __forceinline__ void cpasync16(uint32_t dst, const void* src) {
    asm volatile("cp.async.cg.shared.global [%0], [%1], 16;" :: "r"(dst), "l"(src));
}
#define CP_COMMIT() asm volatile("cp.async.commit_group;" ::: "memory")
#define CP_WAIT0()  asm volatile("cp.async.wait_group 0;" ::: "memory")

__device__ __forceinline__ uint32_t h2pack(float lo, float hi) {
    uint32_t r;
    asm("cvt.rn.f16x2.f32 %0, %1, %2;" : "=r"(r) : "f"(hi), "f"(lo));
    return r;
}
// u32 slot of even element e within pair-interleaved stream
__device__ __forceinline__ int pslot(int e) {
    int p = (e >> 1) & 7;
    return ((e >> 4) << 3) + (((p & 3) << 1) | (p >> 2));
}
// D += A(16x16) * B(16x8), fp16 inputs, fp32 accum
__device__ __forceinline__ void mma16(float* d, const uint32_t* a, uint32_t b0, uint32_t b1) {
    asm volatile(
        "mma.sync.aligned.m16n8k16.row.col.f32.f16.f16.f32 "
        "{%0,%1,%2,%3}, {%4,%5,%6,%7}, {%8,%9}, {%0,%1,%2,%3};"
        : "+f"(d[0]), "+f"(d[1]), "+f"(d[2]), "+f"(d[3])
        : "r"(a[0]), "r"(a[1]), "r"(a[2]), "r"(a[3]), "r"(b0), "r"(b1));
}

// ---------------------------------------------------------------------------
// W pre-pass: wk/wq/wv -> g_wh; w_att -> g_waH (both pair-interleaved fp16).
// ---------------------------------------------------------------------------
__global__ void w_pre(const float* __restrict__ wk, const float* __restrict__ wq,
                      const float* __restrict__ wv, const float* __restrict__ wa)
{
    int idx = blockIdx.x * 256 + threadIdx.x;   // 0..16383
    if (idx < 12288) {
        int r = idx >> 6, c4 = (idx & 63) << 2;
        const float* wsrc = (r < 64) ? wk + r * 256
                          : (r < 128 ? wq + (r - 64) * 256 : wv + (r - 128) * 256);
        float4 v = *(const float4*)(wsrc + c4);
        int base = r * 128 + ((c4 >> 4) << 3);
        int pb = (c4 >> 1) & 7;
        g_wh[base + (((pb & 3) << 1) | (pb >> 2))]   = h2pack(v.x, v.y);
        int pb1 = pb + 1;
        g_wh[base + (((pb1 & 3) << 1) | (pb1 >> 2))] = h2pack(v.z, v.w);
    } else {
        int i2 = idx - 12288;                   // 0..4095
        int r = i2 >> 4, c4 = (i2 & 15) << 2;
        float4 v = *(const float4*)(wa + r * 64 + c4);
        int base = r * 32 + ((c4 >> 4) << 3);
        int pb = (c4 >> 1) & 7;
        g_waH[base + (((pb & 3) << 1) | (pb >> 2))]   = h2pack(v.x, v.y);
        int pb1 = pb + 1;
        g_waH[base + (((pb1 & 3) << 1) | (pb1 >> 2))] = h2pack(v.z, v.w);
    }
}

// ---------------------------------------------------------------------------
// Projection via mma.sync fp16  (unchanged from R12/R14 — known-good)
// ---------------------------------------------------------------------------
__global__ __launch_bounds__(256, 2) void proj_kernel(
    const float* __restrict__ x,
    const float* __restrict__ bk, const float* __restrict__ bq,
    const float* __restrict__ bv)
{
    extern __shared__ char ps[];
    __half* Wh = (__half*)ps;                 // 2 bufs x [192][80] halves
    float*  xs = (float*)(ps + 61440);        // 2 bufs x [64][68] f32

    const int b  = blockIdx.y;
    const int n0 = blockIdx.x << 6;
    const int tid = threadIdx.x;
    const int lane = tid & 31, w = tid >> 5;
    const int tig = lane & 3, gid = lane >> 2;
    const int wm = w & 3, wn = w >> 2;
    const float* xb = x + (size_t)b * C * N;

    auto stageW = [&](int kc, int bw) {
        const char* src = (const char*)g_wh;
        #pragma unroll
        for (int k = 0; k < 6; k++) {
            int u = tid + (k << 8);
            int row = u >> 3, c16 = u & 7;
            cpasync16(smem_u32(Wh + bw * 15360 + row * 80 + c16 * 8),
                      src + row * 512 + kc * 128 + c16 * 16);
        }
    };
    auto stageX = [&](int kc, int bw) {
        #pragma unroll
        for (int k = 0; k < 4; k++) {
            int u = tid + (k << 8);
            int crow = u >> 4, nu = u & 15;
            cpasync16(smem_u32(xs + bw * 4352 + crow * 68 + (nu << 2)),
                      xb + (size_t)(kc * 64 + crow) * N + n0 + (nu << 2));
        }
    };

    stageW(0, 0); stageX(0, 0); CP_COMMIT();

    float D[3][4][4];
    #pragma unroll
    for (int mi = 0; mi < 3; mi++)
        #pragma unroll
        for (int ni = 0; ni < 4; ni++)
            #pragma unroll
            for (int i = 0; i < 4; i++) D[mi][ni][i] = 0.f;

    for (int kc = 0; kc < 4; kc++) {
        const int bufc = kc & 1;
        CP_WAIT0();
        __syncthreads();
        if (kc < 3) { stageW(kc + 1, bufc ^ 1); stageX(kc + 1, bufc ^ 1); CP_COMMIT(); }

        const __half* Wc = Wh + bufc * 15360;
        const float*  Xc = xs + bufc * 4352;
        #pragma unroll
        for (int ks = 0; ks < 4; ks++) {
            uint32_t A[3][4];
            #pragma unroll
            for (int mi = 0; mi < 3; mi++) {
                int r1 = wm * 16 + 64 * mi + gid;
                uint2 lo = *(const uint2*)&Wc[r1 * 80 + ks * 16 + tig * 4];
                uint2 hi = *(const uint2*)&Wc[(r1 + 8) * 80 + ks * 16 + tig * 4];
                A[mi][0] = lo.x; A[mi][1] = hi.x; A[mi][2] = lo.y; A[mi][3] = hi.y;
            }
            #pragma unroll
            for (int ni = 0; ni < 4; ni++) {
                int n  = wn * 32 + ni * 8 + gid;
                int cb = ks * 16 + 2 * tig;
                uint32_t b0 = h2pack(Xc[cb * 68 + n],       Xc[(cb + 1) * 68 + n]);
                uint32_t b1 = h2pack(Xc[(cb + 8) * 68 + n], Xc[(cb + 9) * 68 + n]);
                #pragma unroll
                for (int mi = 0; mi < 3; mi++) mma16(D[mi][ni], A[mi], b0, b1);
            }
        }
    }

    const float sc = 0.0625f;
    const int nb2 = n0 + wn * 32;
    const int e0 = wm * 16 + gid;

    {   // K (mi=0): pairs along e via shfl_xor(4)
        float bk0 = bk[e0], bk8 = bk[e0 + 8];
        uint32_t* Kp = (uint32_t*)g_fK + (size_t)b * N * 32;
        const bool even = (gid & 1) == 0;
        #pragma unroll
        for (int ni = 0; ni < 4; ni++) {
            float c0 = D[0][ni][0] * sc + bk0, c1 = D[0][ni][1] * sc + bk0;
            float c2 = D[0][ni][2] * sc + bk8, c3 = D[0][ni][3] * sc + bk8;
            float p0 = __shfl_xor_sync(0xffffffffu, c0, 4);
            float p1 = __shfl_xor_sync(0xffffffffu, c1, 4);
            float p2 = __shfl_xor_sync(0xffffffffu, c2, 4);
            float p3 = __shfl_xor_sync(0xffffffffu, c3, 4);
            int n = nb2 + ni * 8 + 2 * tig;
            if (even) {
                Kp[(size_t)n * 32 + pslot(e0)]     = h2pack(c0, p0);
                Kp[(size_t)n * 32 + pslot(e0 + 8)] = h2pack(c2, p2);
            } else {
                Kp[(size_t)(n + 1) * 32 + pslot(e0 - 1)] = h2pack(p1, c1);
                Kp[(size_t)(n + 1) * 32 + pslot(e0 + 7)] = h2pack(p3, c3);
            }
        }
    }
    {   // Q (mi=1): fp32 [n][e]
        float bq0 = bq[e0], bq8 = bq[e0 + 8];
        float* Qp = g_gT + (size_t)b * N * 64;
        #pragma unroll
        for (int ni = 0; ni < 4; ni++) {
            int n = nb2 + ni * 8 + 2 * tig;
            Qp[(size_t)n * 64 + e0]           = D[1][ni][0] * sc + bq0;
            Qp[(size_t)(n + 1) * 64 + e0]     = D[1][ni][1] * sc + bq0;
            Qp[(size_t)n * 64 + e0 + 8]       = D[1][ni][2] * sc + bq8;
            Qp[(size_t)(n + 1) * 64 + e0 + 8] = D[1][ni][3] * sc + bq8;
        }
    }
    {   // V (mi=2): pairs along n in-thread
        float bv0 = bv[e0], bv8 = bv[e0 + 8];
        uint32_t* Vp = (uint32_t*)g_hV + (size_t)b * 64 * 2048;
        #pragma unroll
        for (int ni = 0; ni < 4; ni++) {
            int n = nb2 + ni * 8 + 2 * tig;
            int slot = pslot(n);
            Vp[(size_t)e0 * 2048 + slot]       = h2pack(D[2][ni][0] * sc + bv0,
                                                        D[2][ni][1] * sc + bv0);
            Vp[(size_t)(e0 + 8) * 2048 + slot] = h2pack(D[2][ni][2] * sc + bv8,
                                                        D[2][ni][3] * sc + bv8);
        }
    }
}

// ---------------------------------------------------------------------------
// Flash attention + FUSED output projection + residual.
// Main loop unchanged (known-good). Epilogue: O-frags are directly the
// A-frags of the out GEMM over e; w_att staged into freed K/V smem; y
// streamed through freed Psm in 4 quarter-c passes.
// grid (N/128, B), 256 thr, smem 77824 B, 2 CTAs/SM.
// ---------------------------------------------------------------------------
static constexpr int KHALF = 5120;
static constexpr int NT = N / 64;

__global__ __launch_bounds__(256, 2) void flash_mma(
    const float* __restrict__ x, const float* __restrict__ b_att,
    const float* __restrict__ gamma, float* __restrict__ y)
{
    extern __shared__ char sraw[];
    __half* Ks = (__half*)sraw;                 // 2 bufs [64][80]h
    __half* Vs = (__half*)(sraw + 20480);       // 2 bufs [64][80]h
    float*  Psm = (float*)(sraw + 40960);       // [128][72]f (Q stage / Yt)

    const int tid = threadIdx.x;
    const int lane = tid & 31, w = tid >> 5;
    const int tig = lane & 3, gid = lane >> 2;
    const int b = blockIdx.y, q0 = blockIdx.x << 7;

    const __half* Kg = g_fK + (size_t)b * N * E;
    const __half* Vg = g_hV + (size_t)b * E * N;
    const float*  Qg = g_gT + ((size_t)b * N + q0) * E;

    const int srow = tid >> 3, schunk = (tid & 7) << 3;

    for (int i = tid; i < 2048; i += 256) {
        int row = i >> 4, c4 = (i & 15) << 2;
        cpasync16(smem_u32(Psm + row * 72 + c4), Qg + row * 64 + c4);
    }
    #pragma unroll
    for (int p = 0; p < 2; p++) {
        int row = srow + 32 * p;
        cpasync16(smem_u32(Ks + row * 80 + schunk), Kg + (size_t)row * 64 + schunk);
        cpasync16(smem_u32(Vs + row * 80 + schunk), Vg + (size_t)row * N + schunk);
    }
    CP_COMMIT();
    CP_WAIT0();
    __syncthreads();

    uint32_t qa[4][4];
    {
        const float* Qs = Psm + (w * 16) * 72;
        #pragma unroll
        for (int ks = 0; ks < 4; ks++) {
            int e0 = 16 * ks + 2 * tig;
            qa[ks][0] = h2pack(Qs[gid * 72 + e0],           Qs[gid * 72 + e0 + 1]);
            qa[ks][1] = h2pack(Qs[(gid + 8) * 72 + e0],     Qs[(gid + 8) * 72 + e0 + 1]);
            qa[ks][2] = h2pack(Qs[gid * 72 + e0 + 8],       Qs[gid * 72 + e0 + 9]);
            qa[ks][3] = h2pack(Qs[(gid + 8) * 72 + e0 + 8], Qs[(gid + 8) * 72 + e0 + 9]);
        }
    }
    __syncthreads();

    float O[8][4];
    #pragma unroll
    for (int j = 0; j < 8; j++)
        #pragma unroll
        for (int i = 0; i < 4; i++) O[j][i] = 0.f;
    float m0 = -1e30f, m1 = -1e30f, l0 = 0.f, l1 = 0.f;

    for (int t = 0; t < NT; ++t) {
        const int buf = t & 1, nb = buf ^ 1;
        const bool pref = (t < NT - 1);
        const int k0n = (t + 1) << 6;

        if (pref) {
            #pragma unroll
            for (int p = 0; p < 2; p++) {
                int row = srow + 32 * p;
                cpasync16(smem_u32(Ks + nb * KHALF + row * 80 + schunk),
                          Kg + (size_t)(k0n + row) * 64 + schunk);
                cpasync16(smem_u32(Vs + nb * KHALF + row * 80 + schunk),
                          Vg + (size_t)row * N + k0n + schunk);
            }
            CP_COMMIT();
        }

        float S[8][4];
        #pragma unroll
        for (int j = 0; j < 8; j++)
            #pragma unroll
            for (int i = 0; i < 4; i++) S[j][i] = 0.f;
        {
            const __half* Kh = Ks + buf * KHALF;
            #pragma unroll
            for (int ks = 0; ks < 4; ks++) {
                int off = ks * 16 + tig * 4;
                #pragma unroll
                for (int j = 0; j < 8; j++) {
                    uint2 bb = *(const uint2*)&Kh[(gid + 8 * j) * 80 + off];
                    mma16(S[j], qa[ks], bb.x, bb.y);
                }
            }
        }

        float c0m = -1e30f, c1m = -1e30f;
        #pragma unroll
        for (int j = 0; j < 8; j++) {
            c0m = fmaxf(c0m, fmaxf(S[j][0], S[j][1]));
            c1m = fmaxf(c1m, fmaxf(S[j][2], S[j][3]));
        }
        c0m = fmaxf(c0m, __shfl_xor_sync(0xffffffffu, c0m, 1));
        c0m = fmaxf(c0m, __shfl_xor_sync(0xffffffffu, c0m, 2));
        c1m = fmaxf(c1m, __shfl_xor_sync(0xffffffffu, c1m, 1));
        c1m = fmaxf(c1m, __shfl_xor_sync(0xffffffffu, c1m, 2));
        float mn0 = fmaxf(m0, c0m), mn1 = fmaxf(m1, c1m);
        bool need = (mn0 > m0) || (mn1 > m1);
        float a0 = __expf(m0 - mn0), a1 = __expf(m1 - mn1);
        m0 = mn0; m1 = mn1;

        float s0 = 0.f, s1 = 0.f;
        #pragma unroll
        for (int j = 0; j < 8; j++) {
            S[j][0] = __expf(S[j][0] - m0); S[j][1] = __expf(S[j][1] - m0);
            S[j][2] = __expf(S[j][2] - m1); S[j][3] = __expf(S[j][3] - m1);
            s0 += S[j][0] + S[j][1];
            s1 += S[j][2] + S[j][3];
        }
        s0 += __shfl_xor_sync(0xffffffffu, s0, 1);
        s0 += __shfl_xor_sync(0xffffffffu, s0, 2);
        s1 += __shfl_xor_sync(0xffffffffu, s1, 1);
        s1 += __shfl_xor_sync(0xffffffffu, s1, 2);
        l0 = l0 * a0 + s0;
        l1 = l1 * a1 + s1;
        if (__any_sync(0xffffffffu, need)) {
            #pragma unroll
            for (int j = 0; j < 8; j++) {
                O[j][0] *= a0; O[j][1] *= a0; O[j][2] *= a1; O[j][3] *= a1;
            }
        }

        {
            const __half* Vh = Vs + buf * KHALF;
            #pragma unroll
            for (int m = 0; m < 4; m++) {
                uint32_t pa[4] = {
                    h2pack(S[2 * m][0],     S[2 * m][1]),
                    h2pack(S[2 * m][2],     S[2 * m][3]),
                    h2pack(S[2 * m + 1][0], S[2 * m + 1][1]),
                    h2pack(S[2 * m + 1][2], S[2 * m + 1][3])
                };
                int off = m * 16 + tig * 4;
                #pragma unroll
                for (int j = 0; j < 8; j++) {
                    uint2 vv = *(const uint2*)&Vh[(gid + 8 * j) * 80 + off];
                    mma16(O[j], pa, vv.x, vv.y);
                }
            }
        }

        CP_WAIT0();
        __syncthreads();
    }

    // ================= fused output projection epilogue =================
    // stage w_att fp16 into freed K/V smem (exactly 40960 B)
    {
        __half* Wc = Ks;
        #pragma unroll
        for (int k = 0; k < 8; k++) {
            int u = tid + (k << 8);
            int row = u >> 3, c16 = u & 7;
            cpasync16(smem_u32(Wc + row * 80 + c16 * 8),
                      (const char*)g_waH + row * 128 + c16 * 16);
        }
        CP_COMMIT();
        CP_WAIT0();
    }
    __syncthreads();

    // A-frags of out GEMM = normalized O-frags (no data movement)
    uint32_t pa[4][4];
    {
        float i0 = 1.f / l0, i1 = 1.f / l1;
        #pragma unroll
        for (int ks = 0; ks < 4; ks++) {
            pa[ks][0] = h2pack(O[2 * ks][0] * i0,     O[2 * ks][1] * i0);
            pa[ks][1] = h2pack(O[2 * ks][2] * i1,     O[2 * ks][3] * i1);
            pa[ks][2] = h2pack(O[2 * ks + 1][0] * i0, O[2 * ks + 1][1] * i0);
            pa[ks][3] = h2pack(O[2 * ks + 1][2] * i1, O[2 * ks + 1][3] * i1);
        }
    }

    const __half* Wc = Ks;
    float* Yt = Psm;                      // [64 c][132 n] per quarter
    const int nr = w * 16 + gid;

    #pragma unroll
    for (int cq = 0; cq < 4; cq++) {
        float D2[8][4];
        #pragma unroll
        for (int cj = 0; cj < 8; cj++)
            #pragma unroll
            for (int i = 0; i < 4; i++) D2[cj][i] = 0.f;
        #pragma unroll
        for (int ks = 0; ks < 4; ks++) {
            int off = ks * 16 + tig * 4;
            #pragma unroll
            for (int cj = 0; cj < 8; cj++) {
                uint2 bb = *(const uint2*)&Wc[(cq * 64 + cj * 8 + gid) * 80 + off];
                mma16(D2[cj], pa[ks], bb.x, bb.y);
            }
        }
        // stage transposed into Yt
        #pragma unroll
        for (int cj = 0; cj < 8; cj++) {
            int cl = cj * 8 + 2 * tig;
            Yt[cl * 132 + nr]           = D2[cj][0];
            Yt[(cl + 1) * 132 + nr]     = D2[cj][1];
            Yt[cl * 132 + nr + 8]       = D2[cj][2];
            Yt[(cl + 1) * 132 + nr + 8] = D2[cj][3];
        }
        __syncthreads();
        // stream y = gamma*(D/8 + b_att) + x, coalesced
        for (int u = tid; u < 2048; u += 256) {
            int cr = u >> 5, n4 = (u & 31) << 2;
            int c = cq * 64 + cr;
            float4 o4 = *(const float4*)&Yt[cr * 132 + n4];
            float ba = b_att[c], gm = gamma[c];
            size_t gidx = ((size_t)b * C + c) * N + q0 + n4;
            float4 x4 = *(const float4*)(x + gidx);
            float4 y4;
            y4.x = gm * (o4.x * 0.125f + ba) + x4.x;
            y4.y = gm * (o4.y * 0.125f + ba) + x4.y;
            y4.z = gm * (o4.z * 0.125f + ba) + x4.z;
            y4.w = gm * (o4.w * 0.125f + ba) + x4.w;
            *(float4*)(y + gidx) = y4;
        }
        __syncthreads();
    }
}

// ---------------------------------------------------------------------------
extern "C" void kernel_launch(void* const* d_in, const int* in_sizes, int n_in,
                              void* d_out, int out_size)
{
    const float* x  = (const float*)d_in[0];
    const float* wk = (const float*)d_in[1];
    const float* bk = (const float*)d_in[2];
    const float* wq = (const float*)d_in[3];
    const float* bq = (const float*)d_in[4];
    const float* wv = (const float*)d_in[5];
    const float* bv = (const float*)d_in[6];
    const float* wa = (const float*)d_in[7];
    const float* ba = (const float*)d_in[8];
    const float* gm = (const float*)d_in[9];
    float* y = (float*)d_out;

    cudaFuncSetAttribute(proj_kernel, cudaFuncAttributeMaxDynamicSharedMemorySize, 98304);
    cudaFuncSetAttribute(flash_mma,  cudaFuncAttributeMaxDynamicSharedMemorySize, 77824);

    w_pre<<<64, 256>>>(wk, wq, wv, wa);
    proj_kernel<<<dim3(N / 64, B), 256, 96256>>>(x, bk, bq, bv);
    flash_mma<<<dim3(N / 128, B), 256, 77824>>>(x, ba, gm, y);
}